// round 2
// baseline (speedup 1.0000x reference)
#include <cuda_runtime.h>

// ---------------------------------------------------------------------------
// Hierarchical PCN relaxation, fp32 SIMT baseline.
// Layers: v0 (B,1024), v1 (B,2048), v2 (B,2048), v3 (B,2048)=sensory.
// Per iteration:
//   E1 = v1 - tanh(v0) @ W0^T        (err GEMM, tanh fused into A load)
//   E2 = v2 - tanh(v1) @ W1^T
//   E3 = v3 - tanh(v2) @ W2^T
//   v0' = v0 + DT*(-(v0-mem) - LAMB*sign(v0) + (1-tanh(v0)^2) * (E1 @ W0))
//   v1' = v1 + DT*(-E1 + (1-tanh(v1)^2) * (E2 @ W1))
//   v2' = v2 + DT*(-E2 + (1-tanh(v2)^2) * (E3 @ W2))
//   v3' = v3 - DT*E3*mask
// Output: v3 after 20 iterations.
// ---------------------------------------------------------------------------

namespace {
constexpr int BROWS = 4096;
constexpr int D0 = 1024;
constexpr int D1 = 2048;
constexpr float DT_C = 0.01f;
constexpr float LAMB_C = 0.001f;
constexpr int N_ITERS = 20;
}

// Scratch (allocation-free rule: __device__ globals)
__device__ __align__(16) float g_v0[2][(size_t)BROWS * D0];
__device__ __align__(16) float g_v1[2][(size_t)BROWS * D1];
__device__ __align__(16) float g_v2[2][(size_t)BROWS * D1];
__device__ __align__(16) float g_v3[2][(size_t)BROWS * D1];
__device__ __align__(16) float g_E1[(size_t)BROWS * D1];
__device__ __align__(16) float g_E2[(size_t)BROWS * D1];
__device__ __align__(16) float g_E3[(size_t)BROWS * D1];
__device__ __align__(16) float g_row1[D1];
__device__ __align__(16) float g_row2[D1];

// ---------------------------------------------------------------------------
// GEMM 1: E = Vn - tanh(A) @ W^T
//   A : M x K row-major (vals of layer below), tanh applied on load
//   W : N x K row-major (torch Linear weight), contraction over contiguous k
//   Vn: M x N, E: M x N
// 128x128x16 tile, 256 threads, 8x8 per thread, double-buffered smem.
// ---------------------------------------------------------------------------

#define GEMM_COMPUTE(BUF)                                                     \
    _Pragma("unroll")                                                         \
    for (int kk = 0; kk < 16; kk++) {                                         \
        float4 a0 = *(const float4*)&As[BUF][kk][ty * 4];                     \
        float4 a1 = *(const float4*)&As[BUF][kk][ty * 4 + 64];                \
        float4 b0 = *(const float4*)&Bs[BUF][kk][tx * 4];                     \
        float4 b1 = *(const float4*)&Bs[BUF][kk][tx * 4 + 64];                \
        float av[8] = {a0.x, a0.y, a0.z, a0.w, a1.x, a1.y, a1.z, a1.w};       \
        float bv[8] = {b0.x, b0.y, b0.z, b0.w, b1.x, b1.y, b1.z, b1.w};       \
        _Pragma("unroll")                                                     \
        for (int i = 0; i < 8; i++)                                           \
            _Pragma("unroll")                                                 \
            for (int j = 0; j < 8; j++)                                       \
                acc[i][j] += av[i] * bv[j];                                   \
    }

__global__ __launch_bounds__(256, 2)
void err_gemm(const float* __restrict__ A, const float* __restrict__ Vn,
              const float* __restrict__ W, float* __restrict__ E,
              int M, int N, int K) {
    __shared__ float As[2][16][128];
    __shared__ float Bs[2][16][128];
    const int bm = blockIdx.y * 128;
    const int bn = blockIdx.x * 128;
    const int tid = threadIdx.x;
    const int tx = tid & 15, ty = tid >> 4;
    const int lr = tid >> 2;            // load row within tile (0..63, +64)
    const int lk = (tid & 3) << 2;      // load k offset (0,4,8,12)

    const float* Aptr = A + (size_t)(bm + lr) * K + lk;
    const float* Wptr = W + (size_t)(bn + lr) * K + lk;

    float acc[8][8];
#pragma unroll
    for (int i = 0; i < 8; i++)
#pragma unroll
        for (int j = 0; j < 8; j++) acc[i][j] = 0.f;

    // stage 0 -> smem buf 0
    {
        float4 pa0 = *(const float4*)(Aptr);
        float4 pa1 = *(const float4*)(Aptr + (size_t)64 * K);
        float4 pb0 = *(const float4*)(Wptr);
        float4 pb1 = *(const float4*)(Wptr + (size_t)64 * K);
        As[0][lk + 0][lr] = tanhf(pa0.x); As[0][lk + 1][lr] = tanhf(pa0.y);
        As[0][lk + 2][lr] = tanhf(pa0.z); As[0][lk + 3][lr] = tanhf(pa0.w);
        As[0][lk + 0][lr + 64] = tanhf(pa1.x); As[0][lk + 1][lr + 64] = tanhf(pa1.y);
        As[0][lk + 2][lr + 64] = tanhf(pa1.z); As[0][lk + 3][lr + 64] = tanhf(pa1.w);
        Bs[0][lk + 0][lr] = pb0.x; Bs[0][lk + 1][lr] = pb0.y;
        Bs[0][lk + 2][lr] = pb0.z; Bs[0][lk + 3][lr] = pb0.w;
        Bs[0][lk + 0][lr + 64] = pb1.x; Bs[0][lk + 1][lr + 64] = pb1.y;
        Bs[0][lk + 2][lr + 64] = pb1.z; Bs[0][lk + 3][lr + 64] = pb1.w;
    }
    __syncthreads();

    const int nk = K >> 4;
    int buf = 0;
    for (int kt = 1; kt < nk; kt++) {
        const float* Ap = Aptr + kt * 16;
        const float* Wp = Wptr + kt * 16;
        float4 pa0 = *(const float4*)(Ap);
        float4 pa1 = *(const float4*)(Ap + (size_t)64 * K);
        float4 pb0 = *(const float4*)(Wp);
        float4 pb1 = *(const float4*)(Wp + (size_t)64 * K);

        GEMM_COMPUTE(buf)

        const int nb = buf ^ 1;
        As[nb][lk + 0][lr] = tanhf(pa0.x); As[nb][lk + 1][lr] = tanhf(pa0.y);
        As[nb][lk + 2][lr] = tanhf(pa0.z); As[nb][lk + 3][lr] = tanhf(pa0.w);
        As[nb][lk + 0][lr + 64] = tanhf(pa1.x); As[nb][lk + 1][lr + 64] = tanhf(pa1.y);
        As[nb][lk + 2][lr + 64] = tanhf(pa1.z); As[nb][lk + 3][lr + 64] = tanhf(pa1.w);
        Bs[nb][lk + 0][lr] = pb0.x; Bs[nb][lk + 1][lr] = pb0.y;
        Bs[nb][lk + 2][lr] = pb0.z; Bs[nb][lk + 3][lr] = pb0.w;
        Bs[nb][lk + 0][lr + 64] = pb1.x; Bs[nb][lk + 1][lr + 64] = pb1.y;
        Bs[nb][lk + 2][lr + 64] = pb1.z; Bs[nb][lk + 3][lr + 64] = pb1.w;
        __syncthreads();
        buf = nb;
    }
    GEMM_COMPUTE(buf)

    // epilogue: E = Vn - acc
#pragma unroll
    for (int i = 0; i < 8; i++) {
        const int m = bm + ty * 4 + (i & 3) + (i >> 2) * 64;
        const size_t base = (size_t)m * N + bn;
        float4 v0 = *(const float4*)&Vn[base + tx * 4];
        float4 v1 = *(const float4*)&Vn[base + tx * 4 + 64];
        float4 o0, o1;
        o0.x = v0.x - acc[i][0]; o0.y = v0.y - acc[i][1];
        o0.z = v0.z - acc[i][2]; o0.w = v0.w - acc[i][3];
        o1.x = v1.x - acc[i][4]; o1.y = v1.y - acc[i][5];
        o1.z = v1.z - acc[i][6]; o1.w = v1.w - acc[i][7];
        *(float4*)&E[base + tx * 4] = o0;
        *(float4*)&E[base + tx * 4 + 64] = o1;
    }
}

// ---------------------------------------------------------------------------
// GEMM 2: NV = V + DT*(-e - pen*sign(V) + (1 - tanh(V)^2) * (Eup @ W))
//   Eup: M x K row-major, W: K x N row-major (non-transposed), V,NV: M x N
//   mode 0: e = V - memv[n] broadcast, pen = LAMB  (layer 0)
//   mode 1: e = Elow[m,n],              pen = 0    (layers 1,2)
// ---------------------------------------------------------------------------

__device__ __forceinline__ float upd1(float v, float e, float g, float pen) {
    float t = tanhf(v);
    float s = (v > 0.f) ? 1.f : ((v < 0.f) ? -1.f : 0.f);
    return v + DT_C * (-e - pen * s + (1.f - t * t) * g);
}

__global__ __launch_bounds__(256, 2)
void upd_gemm(const float* __restrict__ Eup, const float* __restrict__ W,
              const float* __restrict__ V, const float* __restrict__ Elow,
              const float* __restrict__ memv, float* __restrict__ NV,
              int M, int N, int K, int mode) {
    __shared__ float As[2][16][128];
    __shared__ float Bs[2][16][128];
    const int bm = blockIdx.y * 128;
    const int bn = blockIdx.x * 128;
    const int tid = threadIdx.x;
    const int tx = tid & 15, ty = tid >> 4;
    const int lr = tid >> 2;
    const int lk = (tid & 3) << 2;
    const int wk = tid >> 5;             // 0..7
    const int wn = (tid & 31) << 2;      // 0..124

    const float* Aptr = Eup + (size_t)(bm + lr) * K + lk;
    const float* Wptr = W + (size_t)wk * N + bn + wn;

    float acc[8][8];
#pragma unroll
    for (int i = 0; i < 8; i++)
#pragma unroll
        for (int j = 0; j < 8; j++) acc[i][j] = 0.f;

    {
        float4 pa0 = *(const float4*)(Aptr);
        float4 pa1 = *(const float4*)(Aptr + (size_t)64 * K);
        float4 pb0 = *(const float4*)(Wptr);
        float4 pb1 = *(const float4*)(Wptr + (size_t)8 * N);
        As[0][lk + 0][lr] = pa0.x; As[0][lk + 1][lr] = pa0.y;
        As[0][lk + 2][lr] = pa0.z; As[0][lk + 3][lr] = pa0.w;
        As[0][lk + 0][lr + 64] = pa1.x; As[0][lk + 1][lr + 64] = pa1.y;
        As[0][lk + 2][lr + 64] = pa1.z; As[0][lk + 3][lr + 64] = pa1.w;
        *(float4*)&Bs[0][wk][wn] = pb0;
        *(float4*)&Bs[0][wk + 8][wn] = pb1;
    }
    __syncthreads();

    const int nk = K >> 4;
    int buf = 0;
    for (int kt = 1; kt < nk; kt++) {
        const float* Ap = Aptr + kt * 16;
        const float* Wp = Wptr + (size_t)(kt * 16) * N;
        float4 pa0 = *(const float4*)(Ap);
        float4 pa1 = *(const float4*)(Ap + (size_t)64 * K);
        float4 pb0 = *(const float4*)(Wp);
        float4 pb1 = *(const float4*)(Wp + (size_t)8 * N);

        GEMM_COMPUTE(buf)

        const int nb = buf ^ 1;
        As[nb][lk + 0][lr] = pa0.x; As[nb][lk + 1][lr] = pa0.y;
        As[nb][lk + 2][lr] = pa0.z; As[nb][lk + 3][lr] = pa0.w;
        As[nb][lk + 0][lr + 64] = pa1.x; As[nb][lk + 1][lr + 64] = pa1.y;
        As[nb][lk + 2][lr + 64] = pa1.z; As[nb][lk + 3][lr + 64] = pa1.w;
        *(float4*)&Bs[nb][wk][wn] = pb0;
        *(float4*)&Bs[nb][wk + 8][wn] = pb1;
        __syncthreads();
        buf = nb;
    }
    GEMM_COMPUTE(buf)

#pragma unroll
    for (int i = 0; i < 8; i++) {
        const int m = bm + ty * 4 + (i & 3) + (i >> 2) * 64;
        const size_t base = (size_t)m * N + bn;
#pragma unroll
        for (int h = 0; h < 2; h++) {
            const int nn = tx * 4 + h * 64;
            float4 v = *(const float4*)&V[base + nn];
            float4 e;
            if (mode == 0) {
                float4 mm = *(const float4*)&memv[bn + nn];
                e.x = v.x - mm.x; e.y = v.y - mm.y;
                e.z = v.z - mm.z; e.w = v.w - mm.w;
            } else {
                e = *(const float4*)&Elow[base + nn];
            }
            const float pen = (mode == 0) ? LAMB_C : 0.f;
            float4 o;
            o.x = upd1(v.x, e.x, acc[i][h * 4 + 0], pen);
            o.y = upd1(v.y, e.y, acc[i][h * 4 + 1], pen);
            o.z = upd1(v.z, e.z, acc[i][h * 4 + 2], pen);
            o.w = upd1(v.w, e.w, acc[i][h * 4 + 3], pen);
            *(float4*)&NV[base + nn] = o;
        }
    }
}

// ---------------------------------------------------------------------------
// Elementwise sensory update: out = v3 - DT * E3 * mask
// ---------------------------------------------------------------------------
__global__ void sensory_upd(const float4* __restrict__ v3,
                            const float4* __restrict__ E3,
                            const int4* __restrict__ mask,
                            float4* __restrict__ out) {
    const int i = blockIdx.x * blockDim.x + threadIdx.x;
    if (i >= BROWS * D1 / 4) return;
    float4 v = v3[i];
    float4 e = E3[i];
    int4 m = mask[i];
    float4 o;
    o.x = v.x - DT_C * e.x * (float)m.x;
    o.y = v.y - DT_C * e.y * (float)m.y;
    o.z = v.z - DT_C * e.z * (float)m.z;
    o.w = v.w - DT_C * e.w * (float)m.w;
    out[i] = o;
}

// ---------------------------------------------------------------------------
// Init helpers: single-row forward (initial vals are batch-uniform) + broadcast
// ---------------------------------------------------------------------------
__global__ void row_gemm(const float* __restrict__ in, const float* __restrict__ W,
                         float* __restrict__ out, int K) {
    const int n = blockIdx.x;
    float s = 0.f;
    for (int k = threadIdx.x; k < K; k += 256)
        s += tanhf(in[k]) * W[(size_t)n * K + k];
#pragma unroll
    for (int o = 16; o; o >>= 1) s += __shfl_down_sync(0xffffffffu, s, o);
    __shared__ float red[8];
    if ((threadIdx.x & 31) == 0) red[threadIdx.x >> 5] = s;
    __syncthreads();
    if (threadIdx.x == 0) {
        float t = 0.f;
#pragma unroll
        for (int w = 0; w < 8; w++) t += red[w];
        out[n] = t;
    }
}

__global__ void bcast_rows(const float* __restrict__ row, float* __restrict__ out,
                           int nmask, long total) {
    long i = (long)blockIdx.x * blockDim.x + threadIdx.x;
    const long stride = (long)gridDim.x * blockDim.x;
    for (; i < total; i += stride) out[i] = row[i & nmask];
}

// ---------------------------------------------------------------------------
// Host orchestration (graph-capturable: kernel launches + D2D memcpyAsync only)
// ---------------------------------------------------------------------------
extern "C" void kernel_launch(void* const* d_in, const int* in_sizes, int n_in,
                              void* d_out, int out_size) {
    (void)in_sizes; (void)n_in; (void)out_size;
    const float* corrupt = (const float*)d_in[0];
    const float* memv    = (const float*)d_in[1];
    const float* W0      = (const float*)d_in[2];
    const float* W1      = (const float*)d_in[3];
    const float* W2      = (const float*)d_in[4];
    const int*   mask    = (const int*)d_in[5];
    float* out = (float*)d_out;

    float *v0, *v1, *v2, *v3, *E1p, *E2p, *E3p, *r1, *r2;
    cudaGetSymbolAddress((void**)&v0, g_v0);
    cudaGetSymbolAddress((void**)&v1, g_v1);
    cudaGetSymbolAddress((void**)&v2, g_v2);
    cudaGetSymbolAddress((void**)&v3, g_v3);
    cudaGetSymbolAddress((void**)&E1p, g_E1);
    cudaGetSymbolAddress((void**)&E2p, g_E2);
    cudaGetSymbolAddress((void**)&E3p, g_E3);
    cudaGetSymbolAddress((void**)&r1, g_row1);
    cudaGetSymbolAddress((void**)&r2, g_row2);

    auto V0 = [&](int b) { return v0 + (size_t)b * BROWS * D0; };
    auto V1 = [&](int b) { return v1 + (size_t)b * BROWS * D1; };
    auto V2 = [&](int b) { return v2 + (size_t)b * BROWS * D1; };
    auto V3 = [&](int b) { return v3 + (size_t)b * BROWS * D1; };

    const dim3 blk(256);
    const dim3 gridD1(D1 / 128, BROWS / 128);
    const dim3 gridD0(D0 / 128, BROWS / 128);

    // --- init: vals[0..2] are batch-uniform; compute one row, broadcast ---
    bcast_rows<<<1024, 256>>>(memv, V0(0), D0 - 1, (long)BROWS * D0);
    row_gemm<<<D1, 256>>>(memv, W0, r1, D0);
    bcast_rows<<<1024, 256>>>(r1, V1(0), D1 - 1, (long)BROWS * D1);
    row_gemm<<<D1, 256>>>(r1, W1, r2, D1);
    bcast_rows<<<1024, 256>>>(r2, V2(0), D1 - 1, (long)BROWS * D1);
    cudaMemcpyAsync(V3(0), corrupt, sizeof(float) * (size_t)BROWS * D1,
                    cudaMemcpyDeviceToDevice, 0);

    // initial errors
    err_gemm<<<gridD1, blk>>>(V0(0), V1(0), W0, E1p, BROWS, D1, D0);
    err_gemm<<<gridD1, blk>>>(V1(0), V2(0), W1, E2p, BROWS, D1, D1);
    err_gemm<<<gridD1, blk>>>(V2(0), V3(0), W2, E3p, BROWS, D1, D1);

    for (int it = 0; it < N_ITERS; it++) {
        const int c = it & 1, n = c ^ 1;
        upd_gemm<<<gridD0, blk>>>(E1p, W0, V0(c), nullptr, memv, V0(n),
                                  BROWS, D0, D1, 0);
        upd_gemm<<<gridD1, blk>>>(E2p, W1, V1(c), E1p, nullptr, V1(n),
                                  BROWS, D1, D1, 1);
        upd_gemm<<<gridD1, blk>>>(E3p, W2, V2(c), E2p, nullptr, V2(n),
                                  BROWS, D1, D1, 1);
        float* v3dst = (it == N_ITERS - 1) ? out : V3(n);
        sensory_upd<<<(BROWS * D1 / 4) / 256, 256>>>(
            (const float4*)V3(c), (const float4*)E3p, (const int4*)mask,
            (float4*)v3dst);
        if (it < N_ITERS - 1) {
            err_gemm<<<gridD1, blk>>>(V0(n), V1(n), W0, E1p, BROWS, D1, D0);
            err_gemm<<<gridD1, blk>>>(V1(n), V2(n), W1, E2p, BROWS, D1, D1);
            err_gemm<<<gridD1, blk>>>(V2(n), V3(n), W2, E3p, BROWS, D1, D1);
        }
    }
}

// round 4
// speedup vs baseline: 2.6417x; 2.6417x over previous
#include <cuda_runtime.h>
#include <cstdint>

// ---------------------------------------------------------------------------
// Hierarchical PCN relaxation — tf32 mma.sync (sm_80-class PTX, runs on the
// Blackwell tensor pipe; tcgen05 PTX is rejected by this toolchain's
// compute_100 virtual target).
//
//   err GEMM:  E_l = round_tf32(v_l - T_{l-1} @ W^T)     (T = tanh(v))
//   upd GEMM:  v_l' = v_l + DT*(-e - pen*sign(v_l) + (1 - T_l^2)*(E_{l+1} @ Wt))
//              epilogue writes T_l' = round_tf32(tanh(v_l'))
//   sensory:   v3' = v3 - DT*E3*mask
//
// GEMM core: 128x128x32 CTA tile, 3-stage cp.async pipeline, 8 warps (4x2),
// warp tile 32x64 via mma.sync.m16n8k8.tf32. All operands pre-rounded to
// tf32 (rna) by their producers, so the mainloop is pure LDS+HMMA.
// ---------------------------------------------------------------------------

namespace {
constexpr int BROWS = 4096;
constexpr int D0 = 1024;
constexpr int D1 = 2048;
constexpr float DT_C = 0.01f;
constexpr float LAMB_C = 0.001f;
constexpr int N_ITERS = 20;

constexpr int BK = 32;
constexpr int STAGES = 3;
constexpr int RS = 36;                         // smem row stride (floats)
constexpr int TILE_F = 128 * RS;               // floats per tile
constexpr int SMEM_BYTES = STAGES * 2 * TILE_F * 4;   // 110592
}

// ------------------------- scratch (__device__ globals) --------------------
__device__ __align__(16) float g_v0[2][(size_t)BROWS * D0];
__device__ __align__(16) float g_v1[2][(size_t)BROWS * D1];
__device__ __align__(16) float g_v2[2][(size_t)BROWS * D1];
__device__ __align__(16) float g_v3[2][(size_t)BROWS * D1];
__device__ __align__(16) float g_E1[(size_t)BROWS * D1];
__device__ __align__(16) float g_E2[(size_t)BROWS * D1];
__device__ __align__(16) float g_E3[(size_t)BROWS * D1];
__device__ __align__(16) float g_T0[(size_t)BROWS * D0];
__device__ __align__(16) float g_T1[(size_t)BROWS * D1];
__device__ __align__(16) float g_T2[(size_t)BROWS * D1];
__device__ __align__(16) float g_W0r[(size_t)D1 * D0];   // rounded W copies
__device__ __align__(16) float g_W1r[(size_t)D1 * D1];
__device__ __align__(16) float g_W2r[(size_t)D1 * D1];
__device__ __align__(16) float g_W0t[(size_t)D0 * D1];   // rounded transposes
__device__ __align__(16) float g_W1t[(size_t)D1 * D1];
__device__ __align__(16) float g_W2t[(size_t)D1 * D1];
__device__ __align__(16) float g_row1[D1];
__device__ __align__(16) float g_row2[D1];

// ------------------------------ helpers ------------------------------------
__device__ __forceinline__ float tf32r(float x) {
    uint32_t u;
    asm("cvt.rna.tf32.f32 %0, %1;" : "=r"(u) : "f"(x));
    return __uint_as_float(u);
}
__device__ __forceinline__ void cp16(void* dst, const void* src) {
    uint32_t d = (uint32_t)__cvta_generic_to_shared(dst);
    asm volatile("cp.async.cg.shared.global [%0], [%1], 16;" :: "r"(d), "l"(src));
}
__device__ __forceinline__ void cp_commit() {
    asm volatile("cp.async.commit_group;" ::: "memory");
}
template <int N>
__device__ __forceinline__ void cp_wait() {
    asm volatile("cp.async.wait_group %0;" :: "n"(N) : "memory");
}
__device__ __forceinline__ void mma8(float* c, const uint32_t* a, const uint32_t* b) {
    asm volatile(
        "mma.sync.aligned.m16n8k8.row.col.f32.tf32.tf32.f32 "
        "{%0,%1,%2,%3}, {%4,%5,%6,%7}, {%8,%9}, {%0,%1,%2,%3};"
        : "+f"(c[0]), "+f"(c[1]), "+f"(c[2]), "+f"(c[3])
        : "r"(a[0]), "r"(a[1]), "r"(a[2]), "r"(a[3]), "r"(b[0]), "r"(b[1]));
}

// ------------------------------- GEMM kernel -------------------------------
// acc[m,n] = sum_k A[bm+m, k] * B[bn+n, k]   (both operands K-contiguous)
// MODE 0 (err): Out = round(X1 - acc)
// MODE 1 (upd, layer0): e = v - X3[n] (memv), pen=LAMB; Out=NV, X2=T updated
// MODE 2 (upd, other):  e = X3[m,n] (Elow),  pen=0
template <int MODE>
__global__ void __launch_bounds__(256)
gemm_tc(const float* __restrict__ A, const float* __restrict__ B,
        const float* __restrict__ X1, float* __restrict__ X2,
        const float* __restrict__ X3, float* __restrict__ Out,
        int N, int K) {
    extern __shared__ float smem[];
    const int tid = threadIdx.x;
    const int bm = blockIdx.y * 128, bn = blockIdx.x * 128;
    const float* gA = A + (size_t)bm * K;
    const float* gB = B + (size_t)bn * K;
    const int nkt = K / BK;

    const int warp = tid >> 5, lane = tid & 31;
    const int m0 = (warp & 3) * 32, n0 = (warp >> 2) * 64;
    const int g = lane >> 2, t4 = lane & 3;

    // per-thread load slots: 4 x 16B for A, 4 for B per stage
    int lrow[4], lcol[4];
#pragma unroll
    for (int i = 0; i < 4; i++) {
        const int c = tid + i * 256;       // 0..1023
        lrow[i] = c >> 3;
        lcol[i] = (c & 7) * 4;
    }

    auto load_stage = [&](int s, int kt) {
        float* sa = smem + s * 2 * TILE_F;
        float* sb = sa + TILE_F;
        const float* a = gA + kt * BK;
        const float* b = gB + kt * BK;
#pragma unroll
        for (int i = 0; i < 4; i++) {
            cp16(sa + lrow[i] * RS + lcol[i], a + (size_t)lrow[i] * K + lcol[i]);
            cp16(sb + lrow[i] * RS + lcol[i], b + (size_t)lrow[i] * K + lcol[i]);
        }
    };

    float acc[2][8][4];
#pragma unroll
    for (int mf = 0; mf < 2; mf++)
#pragma unroll
        for (int nf = 0; nf < 8; nf++)
#pragma unroll
            for (int q = 0; q < 4; q++) acc[mf][nf][q] = 0.f;

    // prologue
#pragma unroll
    for (int s = 0; s < STAGES - 1; s++) { load_stage(s, s); cp_commit(); }

    for (int kt = 0; kt < nkt; kt++) {
        cp_wait<STAGES - 2>();
        __syncthreads();
        const int nl = kt + STAGES - 1;
        if (nl < nkt) load_stage(nl % STAGES, nl);
        cp_commit();

        const float* sa = smem + (kt % STAGES) * 2 * TILE_F;
        const float* sb = sa + TILE_F;
#pragma unroll
        for (int ks = 0; ks < 4; ks++) {
            const int k0 = ks * 8;
            uint32_t af[2][4], bf[8][2];
#pragma unroll
            for (int mf = 0; mf < 2; mf++) {
                const int r = m0 + mf * 16 + g;
                af[mf][0] = __float_as_uint(sa[r * RS + k0 + t4]);
                af[mf][1] = __float_as_uint(sa[(r + 8) * RS + k0 + t4]);
                af[mf][2] = __float_as_uint(sa[r * RS + k0 + t4 + 4]);
                af[mf][3] = __float_as_uint(sa[(r + 8) * RS + k0 + t4 + 4]);
            }
#pragma unroll
            for (int nf = 0; nf < 8; nf++) {
                const int r = n0 + nf * 8 + g;
                bf[nf][0] = __float_as_uint(sb[r * RS + k0 + t4]);
                bf[nf][1] = __float_as_uint(sb[r * RS + k0 + t4 + 4]);
            }
#pragma unroll
            for (int mf = 0; mf < 2; mf++)
#pragma unroll
                for (int nf = 0; nf < 8; nf++)
                    mma8(acc[mf][nf], af[mf], bf[nf]);
        }
    }

    // ------------------------------ epilogue -------------------------------
#pragma unroll
    for (int mf = 0; mf < 2; mf++) {
#pragma unroll
        for (int nf = 0; nf < 8; nf++) {
            const int m1 = bm + m0 + mf * 16 + g;
            const int nn = bn + n0 + nf * 8 + t4 * 2;
            const size_t i1 = (size_t)m1 * N + nn;
            const size_t i2 = (size_t)(m1 + 8) * N + nn;
            const float* ac = acc[mf][nf];
            if (MODE == 0) {
                float2 v1 = *(const float2*)(X1 + i1);
                float2 v2 = *(const float2*)(X1 + i2);
                float2 o1 = make_float2(tf32r(v1.x - ac[0]), tf32r(v1.y - ac[1]));
                float2 o2 = make_float2(tf32r(v2.x - ac[2]), tf32r(v2.y - ac[3]));
                *(float2*)(Out + i1) = o1;
                *(float2*)(Out + i2) = o2;
            } else {
                const float pen = (MODE == 1) ? LAMB_C : 0.f;
                float2 v1 = *(const float2*)(X1 + i1);
                float2 v2 = *(const float2*)(X1 + i2);
                float2 t1 = *(const float2*)(X2 + i1);
                float2 t2 = *(const float2*)(X2 + i2);
                float2 e1, e2;
                if (MODE == 1) {
                    float2 mm = *(const float2*)(X3 + nn);
                    e1 = make_float2(v1.x - mm.x, v1.y - mm.y);
                    e2 = make_float2(v2.x - mm.x, v2.y - mm.y);
                } else {
                    e1 = *(const float2*)(X3 + i1);
                    e2 = *(const float2*)(X3 + i2);
                }
                float vv[4] = {v1.x, v1.y, v2.x, v2.y};
                float tt[4] = {t1.x, t1.y, t2.x, t2.y};
                float ee[4] = {e1.x, e1.y, e2.x, e2.y};
                float nv[4], nt[4];
#pragma unroll
                for (int q = 0; q < 4; q++) {
                    const float deriv = 1.f - tt[q] * tt[q];
                    const float sg = (vv[q] > 0.f) ? 1.f : ((vv[q] < 0.f) ? -1.f : 0.f);
                    nv[q] = vv[q] + DT_C * (-ee[q] - pen * sg + deriv * ac[q]);
                    nt[q] = tf32r(tanhf(nv[q]));
                }
                *(float2*)(Out + i1) = make_float2(nv[0], nv[1]);
                *(float2*)(Out + i2) = make_float2(nv[2], nv[3]);
                *(float2*)(X2 + i1) = make_float2(nt[0], nt[1]);
                *(float2*)(X2 + i2) = make_float2(nt[2], nt[3]);
            }
        }
    }
}

// --------------------------- small helper kernels --------------------------
__global__ void sensory_upd(const float4* __restrict__ v3,
                            const float4* __restrict__ E3,
                            const int4* __restrict__ mask,
                            float4* __restrict__ out) {
    const int i = blockIdx.x * blockDim.x + threadIdx.x;
    if (i >= BROWS * D1 / 4) return;
    float4 v = v3[i];
    float4 e = E3[i];
    int4 m = mask[i];
    float4 o;
    o.x = v.x - DT_C * e.x * (float)m.x;
    o.y = v.y - DT_C * e.y * (float)m.y;
    o.z = v.z - DT_C * e.z * (float)m.z;
    o.w = v.w - DT_C * e.w * (float)m.w;
    out[i] = o;
}

__global__ void row_gemm(const float* __restrict__ in, const float* __restrict__ W,
                         float* __restrict__ out, int K) {
    const int n = blockIdx.x;
    float s = 0.f;
    for (int k = threadIdx.x; k < K; k += 256)
        s += tanhf(in[k]) * W[(size_t)n * K + k];
#pragma unroll
    for (int o = 16; o; o >>= 1) s += __shfl_down_sync(0xffffffffu, s, o);
    __shared__ float red[8];
    if ((threadIdx.x & 31) == 0) red[threadIdx.x >> 5] = s;
    __syncthreads();
    if (threadIdx.x == 0) {
        float t = 0.f;
#pragma unroll
        for (int w = 0; w < 8; w++) t += red[w];
        out[n] = t;
    }
}

// broadcast one row across batch; also write rounded tanh(row)
__global__ void bcast2(const float* __restrict__ row, float* __restrict__ v,
                       float* __restrict__ t, int nmask, long total) {
    long i = (long)blockIdx.x * blockDim.x + threadIdx.x;
    const long stride = (long)gridDim.x * blockDim.x;
    for (; i < total; i += stride) {
        float x = row[i & nmask];
        v[i] = x;
        t[i] = tf32r(tanhf(x));
    }
}

// out[i] = round_tf32(in[i])
__global__ void round_copy(const float* __restrict__ in, float* __restrict__ out,
                           long total) {
    long i = (long)blockIdx.x * blockDim.x + threadIdx.x;
    const long stride = (long)gridDim.x * blockDim.x;
    for (; i < total; i += stride) out[i] = tf32r(in[i]);
}

// out[C,R] = round_tf32(in[R,C]^T)
__global__ void transpose_k(const float* __restrict__ in, float* __restrict__ out,
                            int R, int C) {
    __shared__ float t[32][33];
    const int bx = blockIdx.x * 32, by = blockIdx.y * 32;
#pragma unroll
    for (int i = 0; i < 32; i += 8)
        t[threadIdx.y + i][threadIdx.x] =
            in[(size_t)(by + threadIdx.y + i) * C + bx + threadIdx.x];
    __syncthreads();
#pragma unroll
    for (int i = 0; i < 32; i += 8)
        out[(size_t)(bx + threadIdx.y + i) * R + by + threadIdx.x] =
            tf32r(t[threadIdx.x][threadIdx.y + i]);
}

// ------------------------------ orchestration ------------------------------
extern "C" void kernel_launch(void* const* d_in, const int* in_sizes, int n_in,
                              void* d_out, int out_size) {
    (void)in_sizes; (void)n_in; (void)out_size;
    const float* corrupt = (const float*)d_in[0];
    const float* memv    = (const float*)d_in[1];
    const float* W0      = (const float*)d_in[2];
    const float* W1      = (const float*)d_in[3];
    const float* W2      = (const float*)d_in[4];
    const int*   mask    = (const int*)d_in[5];
    float* out = (float*)d_out;

    float *v0, *v1, *v2, *v3, *E1, *E2, *E3, *T0, *T1, *T2;
    float *W0r, *W1r, *W2r, *W0t, *W1t, *W2t, *r1, *r2;
    cudaGetSymbolAddress((void**)&v0, g_v0);
    cudaGetSymbolAddress((void**)&v1, g_v1);
    cudaGetSymbolAddress((void**)&v2, g_v2);
    cudaGetSymbolAddress((void**)&v3, g_v3);
    cudaGetSymbolAddress((void**)&E1, g_E1);
    cudaGetSymbolAddress((void**)&E2, g_E2);
    cudaGetSymbolAddress((void**)&E3, g_E3);
    cudaGetSymbolAddress((void**)&T0, g_T0);
    cudaGetSymbolAddress((void**)&T1, g_T1);
    cudaGetSymbolAddress((void**)&T2, g_T2);
    cudaGetSymbolAddress((void**)&W0r, g_W0r);
    cudaGetSymbolAddress((void**)&W1r, g_W1r);
    cudaGetSymbolAddress((void**)&W2r, g_W2r);
    cudaGetSymbolAddress((void**)&W0t, g_W0t);
    cudaGetSymbolAddress((void**)&W1t, g_W1t);
    cudaGetSymbolAddress((void**)&W2t, g_W2t);
    cudaGetSymbolAddress((void**)&r1, g_row1);
    cudaGetSymbolAddress((void**)&r2, g_row2);

    cudaFuncSetAttribute(gemm_tc<0>, cudaFuncAttributeMaxDynamicSharedMemorySize, SMEM_BYTES);
    cudaFuncSetAttribute(gemm_tc<1>, cudaFuncAttributeMaxDynamicSharedMemorySize, SMEM_BYTES);
    cudaFuncSetAttribute(gemm_tc<2>, cudaFuncAttributeMaxDynamicSharedMemorySize, SMEM_BYTES);

    auto V0 = [&](int b) { return v0 + (size_t)b * BROWS * D0; };
    auto V1 = [&](int b) { return v1 + (size_t)b * BROWS * D1; };
    auto V2 = [&](int b) { return v2 + (size_t)b * BROWS * D1; };
    auto V3 = [&](int b) { return v3 + (size_t)b * BROWS * D1; };

    // rounded weight copies + transposes
    round_copy<<<512, 256>>>(W0, W0r, (long)D1 * D0);
    round_copy<<<512, 256>>>(W1, W1r, (long)D1 * D1);
    round_copy<<<512, 256>>>(W2, W2r, (long)D1 * D1);
    const dim3 tb(32, 8);
    transpose_k<<<dim3(D0 / 32, D1 / 32), tb>>>(W0, W0t, D1, D0);
    transpose_k<<<dim3(D1 / 32, D1 / 32), tb>>>(W1, W1t, D1, D1);
    transpose_k<<<dim3(D1 / 32, D1 / 32), tb>>>(W2, W2t, D1, D1);

    // init: vals[0..2] batch-uniform -> single-row forward + broadcast (+tanh)
    bcast2<<<1024, 256>>>(memv, V0(0), T0, D0 - 1, (long)BROWS * D0);
    row_gemm<<<D1, 256>>>(memv, W0, r1, D0);
    bcast2<<<1024, 256>>>(r1, V1(0), T1, D1 - 1, (long)BROWS * D1);
    row_gemm<<<D1, 256>>>(r1, W1, r2, D1);
    bcast2<<<1024, 256>>>(r2, V2(0), T2, D1 - 1, (long)BROWS * D1);
    cudaMemcpyAsync(V3(0), corrupt, sizeof(float) * (size_t)BROWS * D1,
                    cudaMemcpyDeviceToDevice, 0);

    const dim3 gD1(D1 / 128, BROWS / 128);   // (16, 32)
    const dim3 gD0(D0 / 128, BROWS / 128);   // (8, 32)

    // initial errors
    gemm_tc<0><<<gD1, 256, SMEM_BYTES>>>(T0, W0r, V1(0), nullptr, nullptr, E1, D1, D0);
    gemm_tc<0><<<gD1, 256, SMEM_BYTES>>>(T1, W1r, V2(0), nullptr, nullptr, E2, D1, D1);
    gemm_tc<0><<<gD1, 256, SMEM_BYTES>>>(T2, W2r, V3(0), nullptr, nullptr, E3, D1, D1);

    for (int it = 0; it < N_ITERS; it++) {
        const int c = it & 1, n = c ^ 1;
        gemm_tc<1><<<gD0, 256, SMEM_BYTES>>>(E1, W0t, V0(c), T0, memv, V0(n), D0, D1);
        gemm_tc<2><<<gD1, 256, SMEM_BYTES>>>(E2, W1t, V1(c), T1, E1, V1(n), D1, D1);
        gemm_tc<2><<<gD1, 256, SMEM_BYTES>>>(E3, W2t, V2(c), T2, E2, V2(n), D1, D1);
        float* v3dst = (it == N_ITERS - 1) ? out : V3(n);
        sensory_upd<<<(BROWS * D1 / 4) / 256, 256>>>(
            (const float4*)V3(c), (const float4*)E3, (const int4*)mask,
            (float4*)v3dst);
        if (it < N_ITERS - 1) {
            gemm_tc<0><<<gD1, 256, SMEM_BYTES>>>(T0, W0r, V1(n), nullptr, nullptr, E1, D1, D0);
            gemm_tc<0><<<gD1, 256, SMEM_BYTES>>>(T1, W1r, V2(n), nullptr, nullptr, E2, D1, D1);
            gemm_tc<0><<<gD1, 256, SMEM_BYTES>>>(T2, W2r, V3(n), nullptr, nullptr, E3, D1, D1);
        }
    }
}

// round 5
// speedup vs baseline: 4.1798x; 1.5822x over previous
#include <cuda_runtime.h>
#include <cuda_bf16.h>
#include <cstdint>

// ---------------------------------------------------------------------------
// Hierarchical PCN relaxation — bf16 mma.sync.m16n8k16 + ldmatrix.
// State (v, E) fp32; GEMM operands (T=tanh(v), E, W) kept as bf16 copies.
//   err GEMM:  E_l = v_l - T_{l-1} @ W^T
//   upd GEMM:  v_l' = v_l + DT*(-e - pen*sign(v_l) + (1 - T_l^2)*(E_{l+1} @ Wt))
//              epilogue writes T_l' = bf16(tanh(v_l'))
//   MODE 3: err3 with fused sensory update (v3' = v3 - DT*E3*mask inline)
// GEMM core: 128x128x64 CTA tile, 3-stage cp.async, 8 warps (4x2),
// warp tile 32x64, ldmatrix.x4 fragments, pad-72 smem rows.
// ---------------------------------------------------------------------------

using bf16 = __nv_bfloat16;

namespace {
constexpr int BROWS = 4096;
constexpr int D0 = 1024;
constexpr int D1 = 2048;
constexpr float DT_C = 0.01f;
constexpr float LAMB_C = 0.001f;
constexpr int N_ITERS = 20;

constexpr int BK = 64;
constexpr int STAGES = 3;
constexpr int RS = 72;                       // smem row stride in bf16 (144B)
constexpr int TILE_B = 128 * RS * 2;         // 18432 bytes per operand tile
constexpr int STAGE_B = 2 * TILE_B;          // 36864
constexpr int SMEM_BYTES = STAGES * STAGE_B; // 110592
}

// ------------------------- scratch (__device__ globals) --------------------
__device__ __align__(16) float g_v0[2][(size_t)BROWS * D0];
__device__ __align__(16) float g_v1[2][(size_t)BROWS * D1];
__device__ __align__(16) float g_v2[2][(size_t)BROWS * D1];
__device__ __align__(16) float g_v3[2][(size_t)BROWS * D1];
__device__ __align__(16) float g_E1[(size_t)BROWS * D1];
__device__ __align__(16) float g_E2[(size_t)BROWS * D1];
__device__ __align__(16) float g_E3[(size_t)BROWS * D1];
__device__ __align__(16) bf16 g_T0b[(size_t)BROWS * D0];
__device__ __align__(16) bf16 g_T1b[(size_t)BROWS * D1];
__device__ __align__(16) bf16 g_T2b[(size_t)BROWS * D1];
__device__ __align__(16) bf16 g_E1b[(size_t)BROWS * D1];
__device__ __align__(16) bf16 g_E2b[(size_t)BROWS * D1];
__device__ __align__(16) bf16 g_E3b[(size_t)BROWS * D1];
__device__ __align__(16) bf16 g_W0b[(size_t)D1 * D0];
__device__ __align__(16) bf16 g_W1b[(size_t)D1 * D1];
__device__ __align__(16) bf16 g_W2b[(size_t)D1 * D1];
__device__ __align__(16) bf16 g_W0tb[(size_t)D0 * D1];
__device__ __align__(16) bf16 g_W1tb[(size_t)D1 * D1];
__device__ __align__(16) bf16 g_W2tb[(size_t)D1 * D1];
__device__ __align__(16) float g_row1[D1];
__device__ __align__(16) float g_row2[D1];

// ------------------------------ helpers ------------------------------------
__device__ __forceinline__ void cp16(void* dst, const void* src) {
    uint32_t d = (uint32_t)__cvta_generic_to_shared(dst);
    asm volatile("cp.async.cg.shared.global [%0], [%1], 16;" :: "r"(d), "l"(src));
}
__device__ __forceinline__ void cp_commit() {
    asm volatile("cp.async.commit_group;" ::: "memory");
}
template <int N>
__device__ __forceinline__ void cp_wait() {
    asm volatile("cp.async.wait_group %0;" :: "n"(N) : "memory");
}
__device__ __forceinline__ void ldsm4(uint32_t* r, uint32_t addr) {
    asm volatile("ldmatrix.sync.aligned.m8n8.x4.shared.b16 {%0,%1,%2,%3}, [%4];"
                 : "=r"(r[0]), "=r"(r[1]), "=r"(r[2]), "=r"(r[3]) : "r"(addr));
}
__device__ __forceinline__ void mma16(float* c, const uint32_t* a, const uint32_t* b) {
    asm volatile(
        "mma.sync.aligned.m16n8k16.row.col.f32.bf16.bf16.f32 "
        "{%0,%1,%2,%3}, {%4,%5,%6,%7}, {%8,%9}, {%0,%1,%2,%3};"
        : "+f"(c[0]), "+f"(c[1]), "+f"(c[2]), "+f"(c[3])
        : "r"(a[0]), "r"(a[1]), "r"(a[2]), "r"(a[3]), "r"(b[0]), "r"(b[1]));
}
__device__ __forceinline__ __nv_bfloat162 tobf2(float x, float y) {
    return __floats2bfloat162_rn(x, y);
}

// ------------------------------- GEMM kernel -------------------------------
// acc[m,n] = sum_k A[bm+m,k] * B[bn+n,k]  (A,B bf16, K-contiguous)
// MODE 0 err:            E = X1 - acc;  Out=E (f32), Xb=bf16(E)
// MODE 1 upd layer0:     e = X1 - X3[n] (memv), pen=LAMB; Out=nv, Xb=bf16(tanh nv)
// MODE 2 upd other:      e = X3[m,n] (Elow f32), pen=0
// MODE 3 err3+sensory:   vnew = X1 - DT*X3*Msk; OutV=vnew; E = vnew - acc
template <int MODE>
__global__ void __launch_bounds__(256)
gemm_bf(const bf16* __restrict__ A, const bf16* __restrict__ B,
        const float* __restrict__ X1, bf16* __restrict__ Xb,
        const float* __restrict__ X3, const int* __restrict__ Msk,
        float* __restrict__ Out, float* __restrict__ OutV, int N, int K) {
    extern __shared__ char smem[];
    const uint32_t sbase = (uint32_t)__cvta_generic_to_shared(smem);
    const int tid = threadIdx.x;
    const int bm = blockIdx.y * 128, bn = blockIdx.x * 128;
    const bf16* gA = A + (size_t)bm * K;
    const bf16* gB = B + (size_t)bn * K;
    const int nkt = K / BK;

    const int warp = tid >> 5, lane = tid & 31;
    const int m0 = (warp & 3) * 32, n0 = (warp >> 2) * 64;
    const int g = lane >> 2, t4 = lane & 3;

    // ldmatrix per-thread byte offsets (within a tile)
    uint32_t aoff[2], boff[4];
#pragma unroll
    for (int mf = 0; mf < 2; mf++)
        aoff[mf] = (uint32_t)((m0 + mf * 16 + (lane & 15)) * (RS * 2) +
                              (lane >> 4) * 16);
#pragma unroll
    for (int nfp = 0; nfp < 4; nfp++)
        boff[nfp] = (uint32_t)((n0 + nfp * 16 + (lane & 7) +
                                ((lane >> 4) & 1) * 8) * (RS * 2) +
                               ((lane >> 3) & 1) * 16);

    // cp.async slots: 4 x 16B per operand per stage per thread
    int lrow[4], lcol[4];
#pragma unroll
    for (int i = 0; i < 4; i++) {
        const int c = tid + i * 256;
        lrow[i] = c >> 3;
        lcol[i] = (c & 7) * 8;      // bf16 element offset
    }

    auto load_stage = [&](int s, int kt) {
        char* base = smem + s * STAGE_B;
        const bf16* a = gA + kt * BK;
        const bf16* b = gB + kt * BK;
#pragma unroll
        for (int i = 0; i < 4; i++) {
            cp16(base + lrow[i] * (RS * 2) + lcol[i] * 2,
                 a + (size_t)lrow[i] * K + lcol[i]);
            cp16(base + TILE_B + lrow[i] * (RS * 2) + lcol[i] * 2,
                 b + (size_t)lrow[i] * K + lcol[i]);
        }
    };

    float acc[2][8][4];
#pragma unroll
    for (int mf = 0; mf < 2; mf++)
#pragma unroll
        for (int nf = 0; nf < 8; nf++)
#pragma unroll
            for (int q = 0; q < 4; q++) acc[mf][nf][q] = 0.f;

#pragma unroll
    for (int s = 0; s < STAGES - 1; s++) { load_stage(s, s); cp_commit(); }

    for (int kt = 0; kt < nkt; kt++) {
        cp_wait<STAGES - 2>();
        __syncthreads();
        const int nl = kt + STAGES - 1;
        if (nl < nkt) load_stage(nl % STAGES, nl);
        cp_commit();

        const uint32_t sa = sbase + (uint32_t)((kt % STAGES) * STAGE_B);
        const uint32_t sb = sa + TILE_B;
#pragma unroll
        for (int ks = 0; ks < 4; ks++) {
            uint32_t af[2][4], bq[4][4];
            ldsm4(af[0], sa + aoff[0] + ks * 32);
            ldsm4(af[1], sa + aoff[1] + ks * 32);
#pragma unroll
            for (int nfp = 0; nfp < 4; nfp++)
                ldsm4(bq[nfp], sb + boff[nfp] + ks * 32);
#pragma unroll
            for (int mf = 0; mf < 2; mf++)
#pragma unroll
                for (int nf = 0; nf < 8; nf++)
                    mma16(acc[mf][nf], af[mf], &bq[nf >> 1][(nf & 1) * 2]);
        }
    }

    // ------------------------------ epilogue -------------------------------
#pragma unroll
    for (int mf = 0; mf < 2; mf++) {
#pragma unroll
        for (int nf = 0; nf < 8; nf++) {
            const int m1 = bm + m0 + mf * 16 + g;
            const int nn = bn + n0 + nf * 8 + t4 * 2;
            const size_t i1 = (size_t)m1 * N + nn;
            const size_t i2 = (size_t)(m1 + 8) * N + nn;
            const float* ac = acc[mf][nf];
            if (MODE == 0 || MODE == 3) {
                float2 v1 = *(const float2*)(X1 + i1);
                float2 v2 = *(const float2*)(X1 + i2);
                if (MODE == 3) {
                    float2 e1 = *(const float2*)(X3 + i1);
                    float2 e2 = *(const float2*)(X3 + i2);
                    int2 m1i = *(const int2*)(Msk + i1);
                    int2 m2i = *(const int2*)(Msk + i2);
                    v1.x -= DT_C * e1.x * (float)m1i.x;
                    v1.y -= DT_C * e1.y * (float)m1i.y;
                    v2.x -= DT_C * e2.x * (float)m2i.x;
                    v2.y -= DT_C * e2.y * (float)m2i.y;
                    *(float2*)(OutV + i1) = v1;
                    *(float2*)(OutV + i2) = v2;
                }
                float2 o1 = make_float2(v1.x - ac[0], v1.y - ac[1]);
                float2 o2 = make_float2(v2.x - ac[2], v2.y - ac[3]);
                *(float2*)(Out + i1) = o1;
                *(float2*)(Out + i2) = o2;
                *(__nv_bfloat162*)(Xb + i1) = tobf2(o1.x, o1.y);
                *(__nv_bfloat162*)(Xb + i2) = tobf2(o2.x, o2.y);
            } else {
                const float pen = (MODE == 1) ? LAMB_C : 0.f;
                float2 v1 = *(const float2*)(X1 + i1);
                float2 v2 = *(const float2*)(X1 + i2);
                __nv_bfloat162 tb1 = *(const __nv_bfloat162*)(Xb + i1);
                __nv_bfloat162 tb2 = *(const __nv_bfloat162*)(Xb + i2);
                float2 e1, e2;
                if (MODE == 1) {
                    float2 mm = *(const float2*)(X3 + nn);
                    e1 = make_float2(v1.x - mm.x, v1.y - mm.y);
                    e2 = make_float2(v2.x - mm.x, v2.y - mm.y);
                } else {
                    e1 = *(const float2*)(X3 + i1);
                    e2 = *(const float2*)(X3 + i2);
                }
                float vv[4] = {v1.x, v1.y, v2.x, v2.y};
                float tt[4] = {__bfloat162float(tb1.x), __bfloat162float(tb1.y),
                               __bfloat162float(tb2.x), __bfloat162float(tb2.y)};
                float ee[4] = {e1.x, e1.y, e2.x, e2.y};
                float nv[4], nt[4];
#pragma unroll
                for (int q = 0; q < 4; q++) {
                    const float deriv = 1.f - tt[q] * tt[q];
                    const float sg = (vv[q] > 0.f) ? 1.f : ((vv[q] < 0.f) ? -1.f : 0.f);
                    nv[q] = vv[q] + DT_C * (-ee[q] - pen * sg + deriv * ac[q]);
                    nt[q] = tanhf(nv[q]);
                }
                *(float2*)(Out + i1) = make_float2(nv[0], nv[1]);
                *(float2*)(Out + i2) = make_float2(nv[2], nv[3]);
                *(__nv_bfloat162*)(Xb + i1) = tobf2(nt[0], nt[1]);
                *(__nv_bfloat162*)(Xb + i2) = tobf2(nt[2], nt[3]);
            }
        }
    }
}

// --------------------------- small helper kernels --------------------------
__global__ void sensory_upd(const float4* __restrict__ v3,
                            const float4* __restrict__ E3,
                            const int4* __restrict__ mask,
                            float4* __restrict__ out) {
    const int i = blockIdx.x * blockDim.x + threadIdx.x;
    if (i >= BROWS * D1 / 4) return;
    float4 v = v3[i];
    float4 e = E3[i];
    int4 m = mask[i];
    float4 o;
    o.x = v.x - DT_C * e.x * (float)m.x;
    o.y = v.y - DT_C * e.y * (float)m.y;
    o.z = v.z - DT_C * e.z * (float)m.z;
    o.w = v.w - DT_C * e.w * (float)m.w;
    out[i] = o;
}

__global__ void row_gemm(const float* __restrict__ in, const float* __restrict__ W,
                         float* __restrict__ out, int K) {
    const int n = blockIdx.x;
    float s = 0.f;
    for (int k = threadIdx.x; k < K; k += 256)
        s += tanhf(in[k]) * W[(size_t)n * K + k];
#pragma unroll
    for (int o = 16; o; o >>= 1) s += __shfl_down_sync(0xffffffffu, s, o);
    __shared__ float red[8];
    if ((threadIdx.x & 31) == 0) red[threadIdx.x >> 5] = s;
    __syncthreads();
    if (threadIdx.x == 0) {
        float t = 0.f;
#pragma unroll
        for (int w = 0; w < 8; w++) t += red[w];
        out[n] = t;
    }
}

// broadcast row across batch: v fp32 + bf16 tanh
__global__ void bcast2(const float* __restrict__ row, float* __restrict__ v,
                       bf16* __restrict__ t, int nmask, long total) {
    long i = (long)blockIdx.x * blockDim.x + threadIdx.x;
    const long stride = (long)gridDim.x * blockDim.x;
    for (; i < total; i += stride) {
        float x = row[i & nmask];
        v[i] = x;
        t[i] = __float2bfloat16_rn(tanhf(x));
    }
}

__global__ void zero_fill(float* __restrict__ f, bf16* __restrict__ b, long total) {
    long i = (long)blockIdx.x * blockDim.x + threadIdx.x;
    const long stride = (long)gridDim.x * blockDim.x;
    for (; i < total; i += stride) { f[i] = 0.f; b[i] = __float2bfloat16_rn(0.f); }
}

__global__ void round_copy(const float* __restrict__ in, bf16* __restrict__ out,
                           long total) {
    long i = (long)blockIdx.x * blockDim.x + threadIdx.x;
    const long stride = (long)gridDim.x * blockDim.x;
    for (; i < total; i += stride) out[i] = __float2bfloat16_rn(in[i]);
}

// out[C,R] = bf16(in[R,C]^T)
__global__ void transpose_k(const float* __restrict__ in, bf16* __restrict__ out,
                            int R, int C) {
    __shared__ float t[32][33];
    const int bx = blockIdx.x * 32, by = blockIdx.y * 32;
#pragma unroll
    for (int i = 0; i < 32; i += 8)
        t[threadIdx.y + i][threadIdx.x] =
            in[(size_t)(by + threadIdx.y + i) * C + bx + threadIdx.x];
    __syncthreads();
#pragma unroll
    for (int i = 0; i < 32; i += 8)
        out[(size_t)(bx + threadIdx.y + i) * R + by + threadIdx.x] =
            __float2bfloat16_rn(t[threadIdx.x][threadIdx.y + i]);
}

// ------------------------------ orchestration ------------------------------
extern "C" void kernel_launch(void* const* d_in, const int* in_sizes, int n_in,
                              void* d_out, int out_size) {
    (void)in_sizes; (void)n_in; (void)out_size;
    const float* corrupt = (const float*)d_in[0];
    const float* memv    = (const float*)d_in[1];
    const float* W0      = (const float*)d_in[2];
    const float* W1      = (const float*)d_in[3];
    const float* W2      = (const float*)d_in[4];
    const int*   mask    = (const int*)d_in[5];
    float* out = (float*)d_out;

    float *v0, *v1, *v2, *v3, *E1, *E2, *E3, *r1, *r2;
    bf16 *T0b, *T1b, *T2b, *E1b, *E2b, *E3b, *W0b, *W1b, *W2b, *W0tb, *W1tb, *W2tb;
    cudaGetSymbolAddress((void**)&v0, g_v0);
    cudaGetSymbolAddress((void**)&v1, g_v1);
    cudaGetSymbolAddress((void**)&v2, g_v2);
    cudaGetSymbolAddress((void**)&v3, g_v3);
    cudaGetSymbolAddress((void**)&E1, g_E1);
    cudaGetSymbolAddress((void**)&E2, g_E2);
    cudaGetSymbolAddress((void**)&E3, g_E3);
    cudaGetSymbolAddress((void**)&T0b, g_T0b);
    cudaGetSymbolAddress((void**)&T1b, g_T1b);
    cudaGetSymbolAddress((void**)&T2b, g_T2b);
    cudaGetSymbolAddress((void**)&E1b, g_E1b);
    cudaGetSymbolAddress((void**)&E2b, g_E2b);
    cudaGetSymbolAddress((void**)&E3b, g_E3b);
    cudaGetSymbolAddress((void**)&W0b, g_W0b);
    cudaGetSymbolAddress((void**)&W1b, g_W1b);
    cudaGetSymbolAddress((void**)&W2b, g_W2b);
    cudaGetSymbolAddress((void**)&W0tb, g_W0tb);
    cudaGetSymbolAddress((void**)&W1tb, g_W1tb);
    cudaGetSymbolAddress((void**)&W2tb, g_W2tb);
    cudaGetSymbolAddress((void**)&r1, g_row1);
    cudaGetSymbolAddress((void**)&r2, g_row2);

    cudaFuncSetAttribute(gemm_bf<0>, cudaFuncAttributeMaxDynamicSharedMemorySize, SMEM_BYTES);
    cudaFuncSetAttribute(gemm_bf<1>, cudaFuncAttributeMaxDynamicSharedMemorySize, SMEM_BYTES);
    cudaFuncSetAttribute(gemm_bf<2>, cudaFuncAttributeMaxDynamicSharedMemorySize, SMEM_BYTES);
    cudaFuncSetAttribute(gemm_bf<3>, cudaFuncAttributeMaxDynamicSharedMemorySize, SMEM_BYTES);

    auto V0 = [&](int b) { return v0 + (size_t)b * BROWS * D0; };
    auto V1 = [&](int b) { return v1 + (size_t)b * BROWS * D1; };
    auto V2 = [&](int b) { return v2 + (size_t)b * BROWS * D1; };
    auto V3 = [&](int b) { return v3 + (size_t)b * BROWS * D1; };

    // bf16 weight copies + transposes
    round_copy<<<512, 256>>>(W0, W0b, (long)D1 * D0);
    round_copy<<<512, 256>>>(W1, W1b, (long)D1 * D1);
    round_copy<<<512, 256>>>(W2, W2b, (long)D1 * D1);
    const dim3 tb(32, 8);
    transpose_k<<<dim3(D0 / 32, D1 / 32), tb>>>(W0, W0tb, D1, D0);
    transpose_k<<<dim3(D1 / 32, D1 / 32), tb>>>(W1, W1tb, D1, D1);
    transpose_k<<<dim3(D1 / 32, D1 / 32), tb>>>(W2, W2tb, D1, D1);

    // init: vals[0..2] batch-uniform (single-row forward + broadcast)
    bcast2<<<1024, 256>>>(memv, V0(0), T0b, D0 - 1, (long)BROWS * D0);
    row_gemm<<<D1, 256>>>(memv, W0, r1, D0);
    bcast2<<<1024, 256>>>(r1, V1(0), T1b, D1 - 1, (long)BROWS * D1);
    row_gemm<<<D1, 256>>>(r1, W1, r2, D1);
    bcast2<<<1024, 256>>>(r2, V2(0), T2b, D1 - 1, (long)BROWS * D1);
    cudaMemcpyAsync(V3(0), corrupt, sizeof(float) * (size_t)BROWS * D1,
                    cudaMemcpyDeviceToDevice, 0);

    const dim3 gD1(D1 / 128, BROWS / 128);   // (16, 32)
    const dim3 gD0(D0 / 128, BROWS / 128);   // (8, 32)

    // initial errors: E1 = E2 = 0 exactly (forward-pass construction)
    zero_fill<<<1024, 256>>>(E1, E1b, (long)BROWS * D1);
    zero_fill<<<1024, 256>>>(E2, E2b, (long)BROWS * D1);
    gemm_bf<0><<<gD1, 256, SMEM_BYTES>>>(T2b, W2b, V3(0), E3b, nullptr, nullptr,
                                         E3, nullptr, D1, D1);

    for (int it = 0; it < N_ITERS; it++) {
        const int c = it & 1, n = c ^ 1;
        gemm_bf<1><<<gD0, 256, SMEM_BYTES>>>(E1b, W0tb, V0(c), T0b, memv,
                                             nullptr, V0(n), nullptr, D0, D1);
        gemm_bf<2><<<gD1, 256, SMEM_BYTES>>>(E2b, W1tb, V1(c), T1b, E1,
                                             nullptr, V1(n), nullptr, D1, D1);
        gemm_bf<2><<<gD1, 256, SMEM_BYTES>>>(E3b, W2tb, V2(c), T2b, E2,
                                             nullptr, V2(n), nullptr, D1, D1);
        if (it < N_ITERS - 1) {
            gemm_bf<0><<<gD1, 256, SMEM_BYTES>>>(T0b, W0b, V1(n), E1b, nullptr,
                                                 nullptr, E1, nullptr, D1, D0);
            gemm_bf<0><<<gD1, 256, SMEM_BYTES>>>(T1b, W1b, V2(n), E2b, nullptr,
                                                 nullptr, E2, nullptr, D1, D1);
            // err3 with fused sensory: v3(n) = v3(c) - DT*E3*mask, then
            // E3 = v3(n) - T2(n) @ W2^T
            gemm_bf<3><<<gD1, 256, SMEM_BYTES>>>(T2b, W2b, V3(c), E3b, E3,
                                                 mask, E3, V3(n), D1, D1);
        } else {
            // final sensory update -> output
            sensory_upd<<<(BROWS * D1 / 4) / 256, 256>>>(
                (const float4*)V3(c), (const float4*)E3, (const int4*)mask,
                (float4*)out);
        }
    }
}

// round 6
// speedup vs baseline: 6.3970x; 1.5305x over previous
#include <cuda_runtime.h>
#include <cuda_bf16.h>
#include <cstdint>

// ---------------------------------------------------------------------------
// Hierarchical PCN relaxation — bf16 mma.sync.m16n8k16 + ldmatrix, merged
// phase launches, in-place state updates, 2 CTAs/SM.
//
// State fp32 (v0..v3, E1..E3); GEMM operands bf16 (T=tanh(v), E copies, W).
// Per step:  upd_phase  (one launch: v0,v1,v2 in-place updates, 3 sub-GEMMs)
//            err_phase  (one launch: E2, E3+fused-sensory(v3), E1  sub-GEMMs)
// Last step: sensory only (upd GEMMs are dead work).
// ---------------------------------------------------------------------------

using bf16 = __nv_bfloat16;

namespace {
constexpr int BROWS = 4096;
constexpr int D0 = 1024;
constexpr int D1 = 2048;
constexpr float DT_C = 0.01f;
constexpr float LAMB_C = 0.001f;

constexpr int BK = 64;
constexpr int STAGES = 3;
constexpr int RS = 72;                       // smem row stride in bf16
constexpr int TILE_B = 128 * RS * 2;         // 18432 B per operand tile
constexpr int STAGE_B = 2 * TILE_B;          // 36864
constexpr int SMEM_BYTES = STAGES * STAGE_B; // 110592
}

// ------------------------- scratch (__device__ globals) --------------------
__device__ __align__(16) float g_v0[(size_t)BROWS * D0];
__device__ __align__(16) float g_v1[(size_t)BROWS * D1];
__device__ __align__(16) float g_v2[(size_t)BROWS * D1];
__device__ __align__(16) float g_v3[(size_t)BROWS * D1];
__device__ __align__(16) float g_E1[(size_t)BROWS * D1];
__device__ __align__(16) float g_E2[(size_t)BROWS * D1];
__device__ __align__(16) float g_E3[(size_t)BROWS * D1];
__device__ __align__(16) bf16 g_T0b[(size_t)BROWS * D0];
__device__ __align__(16) bf16 g_T1b[(size_t)BROWS * D1];
__device__ __align__(16) bf16 g_T2b[(size_t)BROWS * D1];
__device__ __align__(16) bf16 g_E1b[(size_t)BROWS * D1];
__device__ __align__(16) bf16 g_E2b[(size_t)BROWS * D1];
__device__ __align__(16) bf16 g_E3b[(size_t)BROWS * D1];
__device__ __align__(16) bf16 g_W0b[(size_t)D1 * D0];
__device__ __align__(16) bf16 g_W1b[(size_t)D1 * D1];
__device__ __align__(16) bf16 g_W2b[(size_t)D1 * D1];
__device__ __align__(16) bf16 g_W0tb[(size_t)D0 * D1];
__device__ __align__(16) bf16 g_W1tb[(size_t)D1 * D1];
__device__ __align__(16) bf16 g_W2tb[(size_t)D1 * D1];
__device__ __align__(16) float g_row1[D1];
__device__ __align__(16) float g_row2[D1];

// ------------------------------ helpers ------------------------------------
__device__ __forceinline__ void cp16(void* dst, const void* src) {
    uint32_t d = (uint32_t)__cvta_generic_to_shared(dst);
    asm volatile("cp.async.cg.shared.global [%0], [%1], 16;" :: "r"(d), "l"(src));
}
__device__ __forceinline__ void cp_commit() {
    asm volatile("cp.async.commit_group;" ::: "memory");
}
template <int N>
__device__ __forceinline__ void cp_wait() {
    asm volatile("cp.async.wait_group %0;" :: "n"(N) : "memory");
}
__device__ __forceinline__ void ldsm4(uint32_t* r, uint32_t addr) {
    asm volatile("ldmatrix.sync.aligned.m8n8.x4.shared.b16 {%0,%1,%2,%3}, [%4];"
                 : "=r"(r[0]), "=r"(r[1]), "=r"(r[2]), "=r"(r[3]) : "r"(addr));
}
__device__ __forceinline__ void mma16(float* c, const uint32_t* a, const uint32_t* b) {
    asm volatile(
        "mma.sync.aligned.m16n8k16.row.col.f32.bf16.bf16.f32 "
        "{%0,%1,%2,%3}, {%4,%5,%6,%7}, {%8,%9}, {%0,%1,%2,%3};"
        : "+f"(c[0]), "+f"(c[1]), "+f"(c[2]), "+f"(c[3])
        : "r"(a[0]), "r"(a[1]), "r"(a[2]), "r"(a[3]), "r"(b[0]), "r"(b[1]));
}
__device__ __forceinline__ __nv_bfloat162 tobf2(float x, float y) {
    return __floats2bfloat162_rn(x, y);
}

// ------------------------- sub-GEMM descriptor -----------------------------
// acc[m,n] = sum_k A[bm+m,k]*B[bn+n,k]  (bf16, K-contiguous)
// mode 0 err:          E = X1 - acc;  Out=E, Xb=bf16(E)
// mode 1 upd layer0:   e = X1 - X3[n], pen=LAMB; Out=nv (in place), Xb=tanh
// mode 2 upd other:    e = X3[m,n], pen=0
// mode 3 err3+sensory: vnew = X1 - DT*X3*Msk; OutV=vnew; E=vnew-acc; Xb=bf16(E)
struct Sub {
    const bf16 *A, *B;
    const float* X1;
    bf16* Xb;
    const float* X3;
    const int* Msk;
    float* Out;
    float* OutV;
    int N, K, mode, nbx;   // nbx = N/128
};

__device__ __forceinline__ void gemm_core(const Sub& S, int lbid, char* smem) {
    const uint32_t sbase = (uint32_t)__cvta_generic_to_shared(smem);
    const int tid = threadIdx.x;
    const int bn = (lbid % S.nbx) * 128;
    const int bm = (lbid / S.nbx) * 128;
    const int K = S.K, N = S.N;
    const bf16* gA = S.A + (size_t)bm * K;
    const bf16* gB = S.B + (size_t)bn * K;
    const int nkt = K / BK;

    const int warp = tid >> 5, lane = tid & 31;
    const int m0 = (warp & 3) * 32, n0 = (warp >> 2) * 64;
    const int g = lane >> 2, t4 = lane & 3;

    uint32_t aoff[2], boff[4];
#pragma unroll
    for (int mf = 0; mf < 2; mf++)
        aoff[mf] = (uint32_t)((m0 + mf * 16 + (lane & 15)) * (RS * 2) +
                              (lane >> 4) * 16);
#pragma unroll
    for (int nfp = 0; nfp < 4; nfp++)
        boff[nfp] = (uint32_t)((n0 + nfp * 16 + (lane & 7) +
                                ((lane >> 4) & 1) * 8) * (RS * 2) +
                               ((lane >> 3) & 1) * 16);

    int lrow[4], lcol[4];
#pragma unroll
    for (int i = 0; i < 4; i++) {
        const int c = tid + i * 256;
        lrow[i] = c >> 3;
        lcol[i] = (c & 7) * 8;
    }

    auto load_stage = [&](int s, int kt) {
        char* base = smem + s * STAGE_B;
        const bf16* a = gA + kt * BK;
        const bf16* b = gB + kt * BK;
#pragma unroll
        for (int i = 0; i < 4; i++) {
            cp16(base + lrow[i] * (RS * 2) + lcol[i] * 2,
                 a + (size_t)lrow[i] * K + lcol[i]);
            cp16(base + TILE_B + lrow[i] * (RS * 2) + lcol[i] * 2,
                 b + (size_t)lrow[i] * K + lcol[i]);
        }
    };

    float acc[2][8][4];
#pragma unroll
    for (int mf = 0; mf < 2; mf++)
#pragma unroll
        for (int nf = 0; nf < 8; nf++)
#pragma unroll
            for (int q = 0; q < 4; q++) acc[mf][nf][q] = 0.f;

#pragma unroll
    for (int s = 0; s < STAGES - 1; s++) { load_stage(s, s); cp_commit(); }

    for (int kt = 0; kt < nkt; kt++) {
        cp_wait<STAGES - 2>();
        __syncthreads();
        const int nl = kt + STAGES - 1;
        if (nl < nkt) load_stage(nl % STAGES, nl);
        cp_commit();

        const uint32_t sa = sbase + (uint32_t)((kt % STAGES) * STAGE_B);
        const uint32_t sb = sa + TILE_B;
#pragma unroll
        for (int ks = 0; ks < 4; ks++) {
            uint32_t af[2][4], bq[4][4];
            ldsm4(af[0], sa + aoff[0] + ks * 32);
            ldsm4(af[1], sa + aoff[1] + ks * 32);
#pragma unroll
            for (int nfp = 0; nfp < 4; nfp++)
                ldsm4(bq[nfp], sb + boff[nfp] + ks * 32);
#pragma unroll
            for (int mf = 0; mf < 2; mf++)
#pragma unroll
                for (int nf = 0; nf < 8; nf++)
                    mma16(acc[mf][nf], af[mf], &bq[nf >> 1][(nf & 1) * 2]);
        }
    }

    // ------------------------------ epilogue -------------------------------
    const int mode = S.mode;
#pragma unroll
    for (int mf = 0; mf < 2; mf++) {
#pragma unroll
        for (int nf = 0; nf < 8; nf++) {
            const int m1 = bm + m0 + mf * 16 + g;
            const int nn = bn + n0 + nf * 8 + t4 * 2;
            const size_t i1 = (size_t)m1 * N + nn;
            const size_t i2 = (size_t)(m1 + 8) * N + nn;
            const float* ac = acc[mf][nf];
            if (mode == 0 || mode == 3) {
                float2 v1 = *(const float2*)(S.X1 + i1);
                float2 v2 = *(const float2*)(S.X1 + i2);
                if (mode == 3) {
                    float2 e1 = *(const float2*)(S.X3 + i1);
                    float2 e2 = *(const float2*)(S.X3 + i2);
                    int2 m1i = *(const int2*)(S.Msk + i1);
                    int2 m2i = *(const int2*)(S.Msk + i2);
                    v1.x -= DT_C * e1.x * (float)m1i.x;
                    v1.y -= DT_C * e1.y * (float)m1i.y;
                    v2.x -= DT_C * e2.x * (float)m2i.x;
                    v2.y -= DT_C * e2.y * (float)m2i.y;
                    *(float2*)(S.OutV + i1) = v1;
                    *(float2*)(S.OutV + i2) = v2;
                }
                float2 o1 = make_float2(v1.x - ac[0], v1.y - ac[1]);
                float2 o2 = make_float2(v2.x - ac[2], v2.y - ac[3]);
                *(float2*)(S.Out + i1) = o1;
                *(float2*)(S.Out + i2) = o2;
                *(__nv_bfloat162*)(S.Xb + i1) = tobf2(o1.x, o1.y);
                *(__nv_bfloat162*)(S.Xb + i2) = tobf2(o2.x, o2.y);
            } else {
                const float pen = (mode == 1) ? LAMB_C : 0.f;
                float2 v1 = *(const float2*)(S.X1 + i1);
                float2 v2 = *(const float2*)(S.X1 + i2);
                __nv_bfloat162 tb1 = *(const __nv_bfloat162*)(S.Xb + i1);
                __nv_bfloat162 tb2 = *(const __nv_bfloat162*)(S.Xb + i2);
                float2 e1, e2;
                if (mode == 1) {
                    float2 mm = *(const float2*)(S.X3 + nn);
                    e1 = make_float2(v1.x - mm.x, v1.y - mm.y);
                    e2 = make_float2(v2.x - mm.x, v2.y - mm.y);
                } else {
                    e1 = *(const float2*)(S.X3 + i1);
                    e2 = *(const float2*)(S.X3 + i2);
                }
                float vv[4] = {v1.x, v1.y, v2.x, v2.y};
                float tt[4] = {__bfloat162float(tb1.x), __bfloat162float(tb1.y),
                               __bfloat162float(tb2.x), __bfloat162float(tb2.y)};
                float ee[4] = {e1.x, e1.y, e2.x, e2.y};
                float nv[4], nt[4];
#pragma unroll
                for (int q = 0; q < 4; q++) {
                    const float deriv = 1.f - tt[q] * tt[q];
                    const float sg = (vv[q] > 0.f) ? 1.f : ((vv[q] < 0.f) ? -1.f : 0.f);
                    nv[q] = vv[q] + DT_C * (-ee[q] - pen * sg + deriv * ac[q]);
                    nt[q] = tanhf(nv[q]);
                }
                *(float2*)(S.Out + i1) = make_float2(nv[0], nv[1]);
                *(float2*)(S.Out + i2) = make_float2(nv[2], nv[3]);
                *(__nv_bfloat162*)(S.Xb + i1) = tobf2(nt[0], nt[1]);
                *(__nv_bfloat162*)(S.Xb + i2) = tobf2(nt[2], nt[3]);
            }
        }
    }
}

// One launch, up to 3 sub-GEMMs. n0/n1 = cumulative CTA counts of subs 0,1.
__global__ void __launch_bounds__(256, 2)
gemm_phase(Sub s0, Sub s1, Sub s2, int n0, int n1) {
    extern __shared__ char smem[];
    const int bid = blockIdx.x;
    if (bid < n0)       gemm_core(s0, bid, smem);
    else if (bid < n1)  gemm_core(s1, bid - n0, smem);
    else                gemm_core(s2, bid - n1, smem);
}

// --------------------------- small helper kernels --------------------------
__global__ void sensory_upd(const float4* __restrict__ v3,
                            const float4* __restrict__ E3,
                            const int4* __restrict__ mask,
                            float4* __restrict__ out) {
    const int i = blockIdx.x * blockDim.x + threadIdx.x;
    if (i >= BROWS * D1 / 4) return;
    float4 v = v3[i];
    float4 e = E3[i];
    int4 m = mask[i];
    float4 o;
    o.x = v.x - DT_C * e.x * (float)m.x;
    o.y = v.y - DT_C * e.y * (float)m.y;
    o.z = v.z - DT_C * e.z * (float)m.z;
    o.w = v.w - DT_C * e.w * (float)m.w;
    out[i] = o;
}

__global__ void row_gemm(const float* __restrict__ in, const float* __restrict__ W,
                         float* __restrict__ out, int K) {
    const int n = blockIdx.x;
    float s = 0.f;
    for (int k = threadIdx.x; k < K; k += 256)
        s += tanhf(in[k]) * W[(size_t)n * K + k];
#pragma unroll
    for (int o = 16; o; o >>= 1) s += __shfl_down_sync(0xffffffffu, s, o);
    __shared__ float red[8];
    if ((threadIdx.x & 31) == 0) red[threadIdx.x >> 5] = s;
    __syncthreads();
    if (threadIdx.x == 0) {
        float t = 0.f;
#pragma unroll
        for (int w = 0; w < 8; w++) t += red[w];
        out[n] = t;
    }
}

__global__ void bcast2(const float* __restrict__ row, float* __restrict__ v,
                       bf16* __restrict__ t, int nmask, long total) {
    long i = (long)blockIdx.x * blockDim.x + threadIdx.x;
    const long stride = (long)gridDim.x * blockDim.x;
    for (; i < total; i += stride) {
        float x = row[i & nmask];
        v[i] = x;
        t[i] = __float2bfloat16_rn(tanhf(x));
    }
}

__global__ void zero_fill(float* __restrict__ f, bf16* __restrict__ b, long total) {
    long i = (long)blockIdx.x * blockDim.x + threadIdx.x;
    const long stride = (long)gridDim.x * blockDim.x;
    for (; i < total; i += stride) { f[i] = 0.f; b[i] = __float2bfloat16_rn(0.f); }
}

__global__ void round_copy(const float* __restrict__ in, bf16* __restrict__ out,
                           long total) {
    long i = (long)blockIdx.x * blockDim.x + threadIdx.x;
    const long stride = (long)gridDim.x * blockDim.x;
    for (; i < total; i += stride) out[i] = __float2bfloat16_rn(in[i]);
}

__global__ void transpose_k(const float* __restrict__ in, bf16* __restrict__ out,
                            int R, int C) {
    __shared__ float t[32][33];
    const int bx = blockIdx.x * 32, by = blockIdx.y * 32;
#pragma unroll
    for (int i = 0; i < 32; i += 8)
        t[threadIdx.y + i][threadIdx.x] =
            in[(size_t)(by + threadIdx.y + i) * C + bx + threadIdx.x];
    __syncthreads();
#pragma unroll
    for (int i = 0; i < 32; i += 8)
        out[(size_t)(bx + threadIdx.y + i) * R + by + threadIdx.x] =
            __float2bfloat16_rn(t[threadIdx.x][threadIdx.y + i]);
}

// ------------------------------ orchestration ------------------------------
extern "C" void kernel_launch(void* const* d_in, const int* in_sizes, int n_in,
                              void* d_out, int out_size) {
    (void)in_sizes; (void)n_in; (void)out_size;
    const float* corrupt = (const float*)d_in[0];
    const float* memv    = (const float*)d_in[1];
    const float* W0      = (const float*)d_in[2];
    const float* W1      = (const float*)d_in[3];
    const float* W2      = (const float*)d_in[4];
    const int*   mask    = (const int*)d_in[5];
    float* out = (float*)d_out;

    float *v0, *v1, *v2, *v3, *E1, *E2, *E3, *r1, *r2;
    bf16 *T0b, *T1b, *T2b, *E1b, *E2b, *E3b, *W0b, *W1b, *W2b, *W0tb, *W1tb, *W2tb;
    cudaGetSymbolAddress((void**)&v0, g_v0);
    cudaGetSymbolAddress((void**)&v1, g_v1);
    cudaGetSymbolAddress((void**)&v2, g_v2);
    cudaGetSymbolAddress((void**)&v3, g_v3);
    cudaGetSymbolAddress((void**)&E1, g_E1);
    cudaGetSymbolAddress((void**)&E2, g_E2);
    cudaGetSymbolAddress((void**)&E3, g_E3);
    cudaGetSymbolAddress((void**)&T0b, g_T0b);
    cudaGetSymbolAddress((void**)&T1b, g_T1b);
    cudaGetSymbolAddress((void**)&T2b, g_T2b);
    cudaGetSymbolAddress((void**)&E1b, g_E1b);
    cudaGetSymbolAddress((void**)&E2b, g_E2b);
    cudaGetSymbolAddress((void**)&E3b, g_E3b);
    cudaGetSymbolAddress((void**)&W0b, g_W0b);
    cudaGetSymbolAddress((void**)&W1b, g_W1b);
    cudaGetSymbolAddress((void**)&W2b, g_W2b);
    cudaGetSymbolAddress((void**)&W0tb, g_W0tb);
    cudaGetSymbolAddress((void**)&W1tb, g_W1tb);
    cudaGetSymbolAddress((void**)&W2tb, g_W2tb);
    cudaGetSymbolAddress((void**)&r1, g_row1);
    cudaGetSymbolAddress((void**)&r2, g_row2);

    cudaFuncSetAttribute(gemm_phase, cudaFuncAttributeMaxDynamicSharedMemorySize,
                         SMEM_BYTES);

    // bf16 weight copies + transposes
    round_copy<<<512, 256>>>(W0, W0b, (long)D1 * D0);
    round_copy<<<512, 256>>>(W1, W1b, (long)D1 * D1);
    round_copy<<<512, 256>>>(W2, W2b, (long)D1 * D1);
    const dim3 tb(32, 8);
    transpose_k<<<dim3(D0 / 32, D1 / 32), tb>>>(W0, W0tb, D1, D0);
    transpose_k<<<dim3(D1 / 32, D1 / 32), tb>>>(W1, W1tb, D1, D1);
    transpose_k<<<dim3(D1 / 32, D1 / 32), tb>>>(W2, W2tb, D1, D1);

    // init: vals[0..2] batch-uniform (single-row forward + broadcast)
    bcast2<<<1024, 256>>>(memv, v0, T0b, D0 - 1, (long)BROWS * D0);
    row_gemm<<<D1, 256>>>(memv, W0, r1, D0);
    bcast2<<<1024, 256>>>(r1, v1, T1b, D1 - 1, (long)BROWS * D1);
    row_gemm<<<D1, 256>>>(r1, W1, r2, D1);
    bcast2<<<1024, 256>>>(r2, v2, T2b, D1 - 1, (long)BROWS * D1);
    cudaMemcpyAsync(v3, corrupt, sizeof(float) * (size_t)BROWS * D1,
                    cudaMemcpyDeviceToDevice, 0);
    zero_fill<<<1024, 256>>>(E1, E1b, (long)BROWS * D1);
    zero_fill<<<1024, 256>>>(E2, E2b, (long)BROWS * D1);

    // sub-GEMM descriptors
    Sub eE1 = {T0b, W0b, v1, E1b, nullptr, nullptr, E1, nullptr, D1, D0, 0, 16};
    Sub eE2 = {T1b, W1b, v2, E2b, nullptr, nullptr, E2, nullptr, D1, D1, 0, 16};
    Sub eE3s = {T2b, W2b, v3, E3b, E3, mask, E3, v3, D1, D1, 3, 16};  // fused sensory
    Sub eE3i = {T2b, W2b, v3, E3b, nullptr, nullptr, E3, nullptr, D1, D1, 0, 16};
    Sub u0 = {E1b, W0tb, v0, T0b, memv, nullptr, v0, nullptr, D0, D1, 1, 8};
    Sub u1 = {E2b, W1tb, v1, T1b, E1, nullptr, v1, nullptr, D1, D1, 2, 16};
    Sub u2 = {E3b, W2tb, v2, T2b, E2, nullptr, v2, nullptr, D1, D1, 2, 16};

    // initial E3 (E1=E2=0 exactly)
    gemm_phase<<<512, 256, SMEM_BYTES>>>(eE3i, eE3i, eE3i, 512, 512);

    // 19 full steps: upd phase (v0,v1,v2) then err phase (sensory+E1,E2,E3)
    for (int it = 0; it < 19; it++) {
        gemm_phase<<<1280, 256, SMEM_BYTES>>>(u1, u2, u0, 512, 1024);
        gemm_phase<<<1536, 256, SMEM_BYTES>>>(eE2, eE3s, eE1, 512, 1024);
    }
    // step 20: only the sensory update matters for the output
    sensory_upd<<<(BROWS * D1 / 4) / 256, 256>>>(
        (const float4*)v3, (const float4*)E3, (const int4*)mask, (float4*)out);
}

// round 8
// speedup vs baseline: 6.8685x; 1.0737x over previous
#include <cuda_runtime.h>
#include <cuda_bf16.h>
#include <cstdint>

// ---------------------------------------------------------------------------
// Hierarchical PCN relaxation — bf16 mma.sync + ldmatrix.
// One launch per iteration: U-phase CTAs (v0,v1,v2 updates) first, E-phase
// CTAs (E1,E2,E3+sensory) spin on a device counter until U completes.
// Cross-phase reads bypass L1 (cp.async.cg operands, __ldcg epilogue loads).
// E1/E2 kept bf16-only. Last iteration trimmed to {u2, eE3s}.
// ---------------------------------------------------------------------------

using bf16 = __nv_bfloat16;

namespace {
constexpr int BROWS = 4096;
constexpr int D0 = 1024;
constexpr int D1 = 2048;
constexpr float DT_C = 0.01f;
constexpr float LAMB_C = 0.001f;

constexpr int BK = 64;
constexpr int STAGES = 3;
constexpr int RS = 72;
constexpr int TILE_B = 128 * RS * 2;
constexpr int STAGE_B = 2 * TILE_B;
constexpr int SMEM_BYTES = STAGES * STAGE_B;   // 110592
}

// ------------------------- scratch (__device__ globals) --------------------
__device__ __align__(16) float g_v0[(size_t)BROWS * D0];
__device__ __align__(16) float g_v1[(size_t)BROWS * D1];
__device__ __align__(16) float g_v2[(size_t)BROWS * D1];
__device__ __align__(16) float g_v3[(size_t)BROWS * D1];
__device__ __align__(16) float g_E3[(size_t)BROWS * D1];
__device__ __align__(16) bf16 g_T0b[(size_t)BROWS * D0];
__device__ __align__(16) bf16 g_T1b[(size_t)BROWS * D1];
__device__ __align__(16) bf16 g_T2b[(size_t)BROWS * D1];
__device__ __align__(16) bf16 g_E1b[(size_t)BROWS * D1];
__device__ __align__(16) bf16 g_E2b[(size_t)BROWS * D1];
__device__ __align__(16) bf16 g_E3b[(size_t)BROWS * D1];
__device__ __align__(16) bf16 g_W0b[(size_t)D1 * D0];
__device__ __align__(16) bf16 g_W1b[(size_t)D1 * D1];
__device__ __align__(16) bf16 g_W2b[(size_t)D1 * D1];
__device__ __align__(16) bf16 g_W0tb[(size_t)D0 * D1];
__device__ __align__(16) bf16 g_W1tb[(size_t)D1 * D1];
__device__ __align__(16) bf16 g_W2tb[(size_t)D1 * D1];
__device__ __align__(16) float g_row1[D1];
__device__ __align__(16) float g_row2[D1];
__device__ int g_ctr[32];

// ------------------------------ helpers ------------------------------------
__device__ __forceinline__ void cp16(void* dst, const void* src) {
    uint32_t d = (uint32_t)__cvta_generic_to_shared(dst);
    asm volatile("cp.async.cg.shared.global [%0], [%1], 16;" :: "r"(d), "l"(src));
}
__device__ __forceinline__ void cp_commit() {
    asm volatile("cp.async.commit_group;" ::: "memory");
}
template <int N>
__device__ __forceinline__ void cp_wait() {
    asm volatile("cp.async.wait_group %0;" :: "n"(N) : "memory");
}
__device__ __forceinline__ void ldsm4(uint32_t* r, uint32_t addr) {
    asm volatile("ldmatrix.sync.aligned.m8n8.x4.shared.b16 {%0,%1,%2,%3}, [%4];"
                 : "=r"(r[0]), "=r"(r[1]), "=r"(r[2]), "=r"(r[3]) : "r"(addr));
}
__device__ __forceinline__ void mma16(float* c, const uint32_t* a, const uint32_t* b) {
    asm volatile(
        "mma.sync.aligned.m16n8k16.row.col.f32.bf16.bf16.f32 "
        "{%0,%1,%2,%3}, {%4,%5,%6,%7}, {%8,%9}, {%0,%1,%2,%3};"
        : "+f"(c[0]), "+f"(c[1]), "+f"(c[2]), "+f"(c[3])
        : "r"(a[0]), "r"(a[1]), "r"(a[2]), "r"(a[3]), "r"(b[0]), "r"(b[1]));
}
__device__ __forceinline__ __nv_bfloat162 tobf2(float x, float y) {
    return __floats2bfloat162_rn(x, y);
}

// ------------------------- sub-GEMM descriptor -----------------------------
// acc[m,n] = sum_k A[bm+m,k]*B[bn+n,k]  (bf16, K-contiguous)
// mode 0 err f32+bf16:  E = X1 - acc; Out f32, Xb bf16      (initial E3)
// mode 4 err bf16-only: E = X1 - acc; Xb bf16               (E1, E2)
// mode 1 upd layer0:    e = X1 - X3[n] (memv), pen=LAMB; Out=nv, Xb=tanh
// mode 2 upd other:     e = bf16 X3b[m,n], pen=0
// mode 3 err3+sensory:  vnew = X1 - DT*X3*Msk; OutV=vnew; E=vnew-acc (f32+bf16)
struct Sub {
    const bf16 *A, *B;
    const float* X1;
    bf16* Xb;
    const float* X3;
    const bf16* X3b;
    const int* Msk;
    float* Out;
    float* OutV;
    int N, K, mode, nbx;
};

__device__ __forceinline__ void gemm_core(const Sub& S, int lbid, char* smem) {
    const uint32_t sbase = (uint32_t)__cvta_generic_to_shared(smem);
    const int tid = threadIdx.x;
    const int bn = (lbid % S.nbx) * 128;
    const int bm = (lbid / S.nbx) * 128;
    const int K = S.K, N = S.N;
    const bf16* gA = S.A + (size_t)bm * K;
    const bf16* gB = S.B + (size_t)bn * K;
    const int nkt = K / BK;

    const int warp = tid >> 5, lane = tid & 31;
    const int m0 = (warp & 3) * 32, n0 = (warp >> 2) * 64;
    const int g = lane >> 2, t4 = lane & 3;

    uint32_t aoff[2], boff[4];
#pragma unroll
    for (int mf = 0; mf < 2; mf++)
        aoff[mf] = (uint32_t)((m0 + mf * 16 + (lane & 15)) * (RS * 2) +
                              (lane >> 4) * 16);
#pragma unroll
    for (int nfp = 0; nfp < 4; nfp++)
        boff[nfp] = (uint32_t)((n0 + nfp * 16 + (lane & 7) +
                                ((lane >> 4) & 1) * 8) * (RS * 2) +
                               ((lane >> 3) & 1) * 16);

    int lrow[4], lcol[4];
#pragma unroll
    for (int i = 0; i < 4; i++) {
        const int c = tid + i * 256;
        lrow[i] = c >> 3;
        lcol[i] = (c & 7) * 8;
    }

    auto load_stage = [&](int s, int kt) {
        char* base = smem + s * STAGE_B;
        const bf16* a = gA + kt * BK;
        const bf16* b = gB + kt * BK;
#pragma unroll
        for (int i = 0; i < 4; i++) {
            cp16(base + lrow[i] * (RS * 2) + lcol[i] * 2,
                 a + (size_t)lrow[i] * K + lcol[i]);
            cp16(base + TILE_B + lrow[i] * (RS * 2) + lcol[i] * 2,
                 b + (size_t)lrow[i] * K + lcol[i]);
        }
    };

    float acc[2][8][4];
#pragma unroll
    for (int mf = 0; mf < 2; mf++)
#pragma unroll
        for (int nf = 0; nf < 8; nf++)
#pragma unroll
            for (int q = 0; q < 4; q++) acc[mf][nf][q] = 0.f;

#pragma unroll
    for (int s = 0; s < STAGES - 1; s++) { load_stage(s, s); cp_commit(); }

    for (int kt = 0; kt < nkt; kt++) {
        cp_wait<STAGES - 2>();
        __syncthreads();
        const int nl = kt + STAGES - 1;
        if (nl < nkt) load_stage(nl % STAGES, nl);
        cp_commit();

        const uint32_t sa = sbase + (uint32_t)((kt % STAGES) * STAGE_B);
        const uint32_t sb = sa + TILE_B;
#pragma unroll
        for (int ks = 0; ks < 4; ks++) {
            uint32_t af[2][4], bq[4][4];
            ldsm4(af[0], sa + aoff[0] + ks * 32);
            ldsm4(af[1], sa + aoff[1] + ks * 32);
#pragma unroll
            for (int nfp = 0; nfp < 4; nfp++)
                ldsm4(bq[nfp], sb + boff[nfp] + ks * 32);
#pragma unroll
            for (int mf = 0; mf < 2; mf++)
#pragma unroll
                for (int nf = 0; nf < 8; nf++)
                    mma16(acc[mf][nf], af[mf], &bq[nf >> 1][(nf & 1) * 2]);
        }
    }

    // ------------------------------ epilogue -------------------------------
    const int mode = S.mode;
#pragma unroll
    for (int mf = 0; mf < 2; mf++) {
#pragma unroll
        for (int nf = 0; nf < 8; nf++) {
            const int m1 = bm + m0 + mf * 16 + g;
            const int nn = bn + n0 + nf * 8 + t4 * 2;
            const size_t i1 = (size_t)m1 * N + nn;
            const size_t i2 = (size_t)(m1 + 8) * N + nn;
            const float* ac = acc[mf][nf];
            if (mode == 0 || mode == 3 || mode == 4) {
                // X1 (v) may have been written by U-phase CTAs in this same
                // launch: bypass L1.
                float2 v1 = __ldcg((const float2*)(S.X1 + i1));
                float2 v2 = __ldcg((const float2*)(S.X1 + i2));
                if (mode == 3) {
                    float2 e1 = *(const float2*)(S.X3 + i1);
                    float2 e2 = *(const float2*)(S.X3 + i2);
                    int2 m1i = *(const int2*)(S.Msk + i1);
                    int2 m2i = *(const int2*)(S.Msk + i2);
                    v1.x -= DT_C * e1.x * (float)m1i.x;
                    v1.y -= DT_C * e1.y * (float)m1i.y;
                    v2.x -= DT_C * e2.x * (float)m2i.x;
                    v2.y -= DT_C * e2.y * (float)m2i.y;
                    *(float2*)(S.OutV + i1) = v1;
                    *(float2*)(S.OutV + i2) = v2;
                }
                float2 o1 = make_float2(v1.x - ac[0], v1.y - ac[1]);
                float2 o2 = make_float2(v2.x - ac[2], v2.y - ac[3]);
                if (mode != 4) {
                    *(float2*)(S.Out + i1) = o1;
                    *(float2*)(S.Out + i2) = o2;
                }
                *(__nv_bfloat162*)(S.Xb + i1) = tobf2(o1.x, o1.y);
                *(__nv_bfloat162*)(S.Xb + i2) = tobf2(o2.x, o2.y);
            } else {
                const float pen = (mode == 1) ? LAMB_C : 0.f;
                float2 v1 = *(const float2*)(S.X1 + i1);
                float2 v2 = *(const float2*)(S.X1 + i2);
                __nv_bfloat162 tb1 = *(const __nv_bfloat162*)(S.Xb + i1);
                __nv_bfloat162 tb2 = *(const __nv_bfloat162*)(S.Xb + i2);
                float2 e1, e2;
                if (mode == 1) {
                    float2 mm = *(const float2*)(S.X3 + nn);
                    e1 = make_float2(v1.x - mm.x, v1.y - mm.y);
                    e2 = make_float2(v2.x - mm.x, v2.y - mm.y);
                } else {
                    __nv_bfloat162 eb1 = *(const __nv_bfloat162*)(S.X3b + i1);
                    __nv_bfloat162 eb2 = *(const __nv_bfloat162*)(S.X3b + i2);
                    e1 = make_float2(__bfloat162float(eb1.x), __bfloat162float(eb1.y));
                    e2 = make_float2(__bfloat162float(eb2.x), __bfloat162float(eb2.y));
                }
                float vv[4] = {v1.x, v1.y, v2.x, v2.y};
                float tt[4] = {__bfloat162float(tb1.x), __bfloat162float(tb1.y),
                               __bfloat162float(tb2.x), __bfloat162float(tb2.y)};
                float ee[4] = {e1.x, e1.y, e2.x, e2.y};
                float nv[4], nt[4];
#pragma unroll
                for (int q = 0; q < 4; q++) {
                    const float deriv = 1.f - tt[q] * tt[q];
                    const float sg = (vv[q] > 0.f) ? 1.f : ((vv[q] < 0.f) ? -1.f : 0.f);
                    nv[q] = vv[q] + DT_C * (-ee[q] - pen * sg + deriv * ac[q]);
                    nt[q] = tanhf(nv[q]);
                }
                *(float2*)(S.Out + i1) = make_float2(nv[0], nv[1]);
                *(float2*)(S.Out + i2) = make_float2(nv[2], nv[3]);
                *(__nv_bfloat162*)(S.Xb + i1) = tobf2(nt[0], nt[1]);
                *(__nv_bfloat162*)(S.Xb + i2) = tobf2(nt[2], nt[3]);
            }
        }
    }
}

// ---------------------- one-launch-per-iteration kernel --------------------
struct IterArgs {
    Sub s[6];
    int cum[6];   // cumulative CTA end offsets per sub
    int nU;       // #U-phase CTAs (phase boundary & spin threshold)
    int* ctr;     // per-iteration counter
};

__global__ void __launch_bounds__(256, 2)
gemm_iter(IterArgs P) {
    extern __shared__ char smem[];
    const int bid = blockIdx.x;
    int si = 0;
#pragma unroll
    for (int i = 0; i < 5; i++) si += (bid >= P.cum[i]) ? 1 : 0;
    const int lb = bid - (si ? P.cum[si - 1] : 0);
    const bool isE = bid >= P.nU;

    if (isE && P.nU > 0) {
        if (threadIdx.x == 0) {
            while (*(volatile int*)P.ctr < P.nU) __nanosleep(64);
        }
        __syncthreads();   // broadcast observation; L1 bypassed on hot reads
    }

    gemm_core(P.s[si], lb, smem);

    if (!isE) {
        __threadfence();       // make this CTA's stores visible at gpu scope
        __syncthreads();       // all threads' fences done
        if (threadIdx.x == 0) atomicAdd(P.ctr, 1);
    }
}

// --------------------------- small helper kernels --------------------------
__global__ void sensory_upd(const float4* __restrict__ v3,
                            const float4* __restrict__ E3,
                            const int4* __restrict__ mask,
                            float4* __restrict__ out) {
    const int i = blockIdx.x * blockDim.x + threadIdx.x;
    if (i >= BROWS * D1 / 4) return;
    float4 v = v3[i];
    float4 e = E3[i];
    int4 m = mask[i];
    float4 o;
    o.x = v.x - DT_C * e.x * (float)m.x;
    o.y = v.y - DT_C * e.y * (float)m.y;
    o.z = v.z - DT_C * e.z * (float)m.z;
    o.w = v.w - DT_C * e.w * (float)m.w;
    out[i] = o;
}

__global__ void row_gemm(const float* __restrict__ in, const float* __restrict__ W,
                         float* __restrict__ out, int K) {
    const int n = blockIdx.x;
    float s = 0.f;
    for (int k = threadIdx.x; k < K; k += 256)
        s += tanhf(in[k]) * W[(size_t)n * K + k];
#pragma unroll
    for (int o = 16; o; o >>= 1) s += __shfl_down_sync(0xffffffffu, s, o);
    __shared__ float red[8];
    if ((threadIdx.x & 31) == 0) red[threadIdx.x >> 5] = s;
    __syncthreads();
    if (threadIdx.x == 0) {
        float t = 0.f;
#pragma unroll
        for (int w = 0; w < 8; w++) t += red[w];
        out[n] = t;
    }
}

__global__ void bcast2(const float* __restrict__ row, float* __restrict__ v,
                       bf16* __restrict__ t, int nmask, long total) {
    long i = (long)blockIdx.x * blockDim.x + threadIdx.x;
    const long stride = (long)gridDim.x * blockDim.x;
    for (; i < total; i += stride) {
        float x = row[i & nmask];
        v[i] = x;
        t[i] = __float2bfloat16_rn(tanhf(x));
    }
}

__global__ void zero_fill_b(bf16* __restrict__ b, long total) {
    long i = (long)blockIdx.x * blockDim.x + threadIdx.x;
    const long stride = (long)gridDim.x * blockDim.x;
    for (; i < total; i += stride) b[i] = __float2bfloat16_rn(0.f);
}

__global__ void zero_ctr(int* c) { if (threadIdx.x < 32) c[threadIdx.x] = 0; }

__global__ void round_copy(const float* __restrict__ in, bf16* __restrict__ out,
                           long total) {
    long i = (long)blockIdx.x * blockDim.x + threadIdx.x;
    const long stride = (long)gridDim.x * blockDim.x;
    for (; i < total; i += stride) out[i] = __float2bfloat16_rn(in[i]);
}

__global__ void transpose_k(const float* __restrict__ in, bf16* __restrict__ out,
                            int R, int C) {
    __shared__ float t[32][33];
    const int bx = blockIdx.x * 32, by = blockIdx.y * 32;
#pragma unroll
    for (int i = 0; i < 32; i += 8)
        t[threadIdx.y + i][threadIdx.x] =
            in[(size_t)(by + threadIdx.y + i) * C + bx + threadIdx.x];
    __syncthreads();
#pragma unroll
    for (int i = 0; i < 32; i += 8)
        out[(size_t)(bx + threadIdx.y + i) * R + by + threadIdx.x] =
            __float2bfloat16_rn(t[threadIdx.x][threadIdx.y + i]);
}

// ------------------------------ orchestration ------------------------------
extern "C" void kernel_launch(void* const* d_in, const int* in_sizes, int n_in,
                              void* d_out, int out_size) {
    (void)in_sizes; (void)n_in; (void)out_size;
    const float* corrupt = (const float*)d_in[0];
    const float* memv    = (const float*)d_in[1];
    const float* W0      = (const float*)d_in[2];
    const float* W1      = (const float*)d_in[3];
    const float* W2      = (const float*)d_in[4];
    const int*   mask    = (const int*)d_in[5];
    float* out = (float*)d_out;

    float *v0, *v1, *v2, *v3, *E3, *r1, *r2;
    int* ctr;
    bf16 *T0b, *T1b, *T2b, *E1b, *E2b, *E3b, *W0b, *W1b, *W2b, *W0tb, *W1tb, *W2tb;
    cudaGetSymbolAddress((void**)&v0, g_v0);
    cudaGetSymbolAddress((void**)&v1, g_v1);
    cudaGetSymbolAddress((void**)&v2, g_v2);
    cudaGetSymbolAddress((void**)&v3, g_v3);
    cudaGetSymbolAddress((void**)&E3, g_E3);
    cudaGetSymbolAddress((void**)&ctr, g_ctr);
    cudaGetSymbolAddress((void**)&T0b, g_T0b);
    cudaGetSymbolAddress((void**)&T1b, g_T1b);
    cudaGetSymbolAddress((void**)&T2b, g_T2b);
    cudaGetSymbolAddress((void**)&E1b, g_E1b);
    cudaGetSymbolAddress((void**)&E2b, g_E2b);
    cudaGetSymbolAddress((void**)&E3b, g_E3b);
    cudaGetSymbolAddress((void**)&W0b, g_W0b);
    cudaGetSymbolAddress((void**)&W1b, g_W1b);
    cudaGetSymbolAddress((void**)&W2b, g_W2b);
    cudaGetSymbolAddress((void**)&W0tb, g_W0tb);
    cudaGetSymbolAddress((void**)&W1tb, g_W1tb);
    cudaGetSymbolAddress((void**)&W2tb, g_W2tb);
    cudaGetSymbolAddress((void**)&r1, g_row1);
    cudaGetSymbolAddress((void**)&r2, g_row2);

    cudaFuncSetAttribute(gemm_iter, cudaFuncAttributeMaxDynamicSharedMemorySize,
                         SMEM_BYTES);

    // ------------------------------- init ----------------------------------
    round_copy<<<512, 256>>>(W0, W0b, (long)D1 * D0);
    round_copy<<<512, 256>>>(W1, W1b, (long)D1 * D1);
    round_copy<<<512, 256>>>(W2, W2b, (long)D1 * D1);
    const dim3 tb(32, 8);
    transpose_k<<<dim3(D0 / 32, D1 / 32), tb>>>(W0, W0tb, D1, D0);
    transpose_k<<<dim3(D1 / 32, D1 / 32), tb>>>(W1, W1tb, D1, D1);
    transpose_k<<<dim3(D1 / 32, D1 / 32), tb>>>(W2, W2tb, D1, D1);

    bcast2<<<1024, 256>>>(memv, v0, T0b, D0 - 1, (long)BROWS * D0);
    row_gemm<<<D1, 256>>>(memv, W0, r1, D0);
    bcast2<<<1024, 256>>>(r1, v1, T1b, D1 - 1, (long)BROWS * D1);
    row_gemm<<<D1, 256>>>(r1, W1, r2, D1);
    bcast2<<<1024, 256>>>(r2, v2, T2b, D1 - 1, (long)BROWS * D1);
    cudaMemcpyAsync(v3, corrupt, sizeof(float) * (size_t)BROWS * D1,
                    cudaMemcpyDeviceToDevice, 0);
    zero_fill_b<<<1024, 256>>>(E1b, (long)BROWS * D1);
    zero_fill_b<<<1024, 256>>>(E2b, (long)BROWS * D1);
    zero_ctr<<<1, 32>>>(ctr);

    // ------------------------- sub-GEMM descriptors ------------------------
    Sub eE1 = {T0b, W0b, v1, E1b, nullptr, nullptr, nullptr, nullptr, nullptr,
               D1, D0, 4, 16};
    Sub eE2 = {T1b, W1b, v2, E2b, nullptr, nullptr, nullptr, nullptr, nullptr,
               D1, D1, 4, 16};
    Sub eE3s = {T2b, W2b, v3, E3b, E3, nullptr, mask, E3, v3, D1, D1, 3, 16};
    Sub eE3i = {T2b, W2b, v3, E3b, nullptr, nullptr, nullptr, E3, nullptr,
                D1, D1, 0, 16};
    Sub u0 = {E1b, W0tb, v0, T0b, memv, nullptr, nullptr, v0, nullptr,
              D0, D1, 1, 8};
    Sub u1 = {E2b, W1tb, v1, T1b, nullptr, E1b, nullptr, v1, nullptr,
              D1, D1, 2, 16};
    Sub u2 = {E3b, W2tb, v2, T2b, nullptr, E2b, nullptr, v2, nullptr,
              D1, D1, 2, 16};

    // initial E3 (E1 = E2 = 0 exactly); no phase dependency
    {
        IterArgs P;
        P.s[0] = eE3i; P.s[1] = eE3i; P.s[2] = eE3i;
        P.s[3] = eE3i; P.s[4] = eE3i; P.s[5] = eE3i;
        P.cum[0] = 512; P.cum[1] = 512; P.cum[2] = 512;
        P.cum[3] = 512; P.cum[4] = 512; P.cum[5] = 512;
        P.nU = 0; P.ctr = ctr + 31;
        gemm_iter<<<512, 256, SMEM_BYTES>>>(P);
    }

    // 18 full steps: one launch each (U: u1,u2,u0 | E: eE2,eE3s,eE1)
    for (int it = 0; it < 18; it++) {
        IterArgs P;
        P.s[0] = u1;  P.s[1] = u2;   P.s[2] = u0;
        P.s[3] = eE2; P.s[4] = eE3s; P.s[5] = eE1;
        P.cum[0] = 512;  P.cum[1] = 1024; P.cum[2] = 1280;
        P.cum[3] = 1792; P.cum[4] = 2304; P.cum[5] = 2816;
        P.nU = 1280; P.ctr = ctr + it;
        gemm_iter<<<2816, 256, SMEM_BYTES>>>(P);
    }
    // step 19 trimmed: only u2 (feeds T2b) and eE3s (v3 sensory + E3) matter
    {
        IterArgs P;
        P.s[0] = u2; P.s[1] = eE3s;
        P.s[2] = eE3s; P.s[3] = eE3s; P.s[4] = eE3s; P.s[5] = eE3s;
        P.cum[0] = 512;  P.cum[1] = 1024; P.cum[2] = 1024;
        P.cum[3] = 1024; P.cum[4] = 1024; P.cum[5] = 1024;
        P.nU = 512; P.ctr = ctr + 18;
        gemm_iter<<<1024, 256, SMEM_BYTES>>>(P);
    }
    // step 20: final sensory update -> output
    sensory_upd<<<(BROWS * D1 / 4) / 256, 256>>>(
        (const float4*)v3, (const float4*)E3, (const int4*)mask, (float4*)out);
}

// round 9
// speedup vs baseline: 7.1496x; 1.0409x over previous
#include <cuda_runtime.h>
#include <cuda_bf16.h>
#include <cstdint>

// ---------------------------------------------------------------------------
// Hierarchical PCN relaxation — bf16 mma.sync + ldmatrix.
// ONE mega-launch for the whole 19-iteration loop: per-sub dependency
// counters (fine-grained producer/consumer), spin-wait with __nanosleep.
// All cross-sub global reads bypass L1 (cp.async.cg operands, __ldcg epilogue).
// Final sensory update fused as tail CTAs of the same launch.
// ---------------------------------------------------------------------------

using bf16 = __nv_bfloat16;

namespace {
constexpr int BROWS = 4096;
constexpr int D0 = 1024;
constexpr int D1 = 2048;
constexpr float DT_C = 0.01f;
constexpr float LAMB_C = 0.001f;

constexpr int BK = 64;
constexpr int STAGES = 3;
constexpr int RS = 72;
constexpr int TILE_B = 128 * RS * 2;
constexpr int STAGE_B = 2 * TILE_B;
constexpr int SMEM_BYTES = STAGES * STAGE_B;   // 110592

constexpr int NFULL = 18;                      // full iterations in mega launch
constexpr int CPI = 2816;                      // CTAs per full iteration
constexpr int GRID_MEGA = 512 + NFULL * CPI + 1024 + 64;
constexpr int CTR_INIT = 19 * 8;               // init-E3 counter slot
}

// ------------------------- scratch (__device__ globals) --------------------
__device__ __align__(16) float g_v0[(size_t)BROWS * D0];
__device__ __align__(16) float g_v1[(size_t)BROWS * D1];
__device__ __align__(16) float g_v2[(size_t)BROWS * D1];
__device__ __align__(16) float g_v3[(size_t)BROWS * D1];
__device__ __align__(16) float g_E3[(size_t)BROWS * D1];
__device__ __align__(16) bf16 g_T0b[(size_t)BROWS * D0];
__device__ __align__(16) bf16 g_T1b[(size_t)BROWS * D1];
__device__ __align__(16) bf16 g_T2b[(size_t)BROWS * D1];
__device__ __align__(16) bf16 g_E1b[(size_t)BROWS * D1];
__device__ __align__(16) bf16 g_E2b[(size_t)BROWS * D1];
__device__ __align__(16) bf16 g_E3b[(size_t)BROWS * D1];
__device__ __align__(16) bf16 g_W0b[(size_t)D1 * D0];
__device__ __align__(16) bf16 g_W1b[(size_t)D1 * D1];
__device__ __align__(16) bf16 g_W2b[(size_t)D1 * D1];
__device__ __align__(16) bf16 g_W0tb[(size_t)D0 * D1];
__device__ __align__(16) bf16 g_W1tb[(size_t)D1 * D1];
__device__ __align__(16) bf16 g_W2tb[(size_t)D1 * D1];
__device__ __align__(16) float g_row1[D1];
__device__ __align__(16) float g_row2[D1];
__device__ int g_ctr[192];

// ------------------------------ helpers ------------------------------------
__device__ __forceinline__ void cp16(void* dst, const void* src) {
    uint32_t d = (uint32_t)__cvta_generic_to_shared(dst);
    asm volatile("cp.async.cg.shared.global [%0], [%1], 16;" :: "r"(d), "l"(src));
}
__device__ __forceinline__ void cp_commit() {
    asm volatile("cp.async.commit_group;" ::: "memory");
}
template <int N>
__device__ __forceinline__ void cp_wait() {
    asm volatile("cp.async.wait_group %0;" :: "n"(N) : "memory");
}
__device__ __forceinline__ void ldsm4(uint32_t* r, uint32_t addr) {
    asm volatile("ldmatrix.sync.aligned.m8n8.x4.shared.b16 {%0,%1,%2,%3}, [%4];"
                 : "=r"(r[0]), "=r"(r[1]), "=r"(r[2]), "=r"(r[3]) : "r"(addr));
}
__device__ __forceinline__ void mma16(float* c, const uint32_t* a, const uint32_t* b) {
    asm volatile(
        "mma.sync.aligned.m16n8k16.row.col.f32.bf16.bf16.f32 "
        "{%0,%1,%2,%3}, {%4,%5,%6,%7}, {%8,%9}, {%0,%1,%2,%3};"
        : "+f"(c[0]), "+f"(c[1]), "+f"(c[2]), "+f"(c[3])
        : "r"(a[0]), "r"(a[1]), "r"(a[2]), "r"(a[3]), "r"(b[0]), "r"(b[1]));
}
__device__ __forceinline__ __nv_bfloat162 tobf2(float x, float y) {
    return __floats2bfloat162_rn(x, y);
}
__device__ __forceinline__ __nv_bfloat162 ldcg_bf2(const bf16* p) {
    unsigned int u = __ldcg((const unsigned int*)p);
    return *reinterpret_cast<__nv_bfloat162*>(&u);
}

// ------------------------- sub-GEMM descriptor -----------------------------
// acc[m,n] = sum_k A[bm+m,k]*B[bn+n,k]  (bf16, K-contiguous)
// mode 0 err f32+bf16:  E = X1 - acc; Out f32, Xb bf16      (initial E3)
// mode 4 err bf16-only: E = X1 - acc; Xb bf16               (E1, E2)
// mode 1 upd layer0:    e = X1 - X3[n] (memv), pen=LAMB; Out=nv, Xb=tanh
// mode 2 upd other:     e = bf16 X3b[m,n], pen=0
// mode 3 err3+sensory:  vnew = X1 - DT*X3*Msk; OutV=vnew; E=vnew-acc (f32+bf16)
struct Sub {
    const bf16 *A, *B;
    const float* X1;
    bf16* Xb;
    const float* X3;
    const bf16* X3b;
    const int* Msk;
    float* Out;
    float* OutV;
    int N, K, mode, nbx;
};

__device__ __forceinline__ void gemm_core(const Sub& S, int lbid, char* smem) {
    const uint32_t sbase = (uint32_t)__cvta_generic_to_shared(smem);
    const int tid = threadIdx.x;
    const int bn = (lbid % S.nbx) * 128;
    const int bm = (lbid / S.nbx) * 128;
    const int K = S.K, N = S.N;
    const bf16* gA = S.A + (size_t)bm * K;
    const bf16* gB = S.B + (size_t)bn * K;
    const int nkt = K / BK;

    const int warp = tid >> 5, lane = tid & 31;
    const int m0 = (warp & 3) * 32, n0 = (warp >> 2) * 64;
    const int g = lane >> 2, t4 = lane & 3;

    uint32_t aoff[2], boff[4];
#pragma unroll
    for (int mf = 0; mf < 2; mf++)
        aoff[mf] = (uint32_t)((m0 + mf * 16 + (lane & 15)) * (RS * 2) +
                              (lane >> 4) * 16);
#pragma unroll
    for (int nfp = 0; nfp < 4; nfp++)
        boff[nfp] = (uint32_t)((n0 + nfp * 16 + (lane & 7) +
                                ((lane >> 4) & 1) * 8) * (RS * 2) +
                               ((lane >> 3) & 1) * 16);

    int lrow[4], lcol[4];
#pragma unroll
    for (int i = 0; i < 4; i++) {
        const int c = tid + i * 256;
        lrow[i] = c >> 3;
        lcol[i] = (c & 7) * 8;
    }

    auto load_stage = [&](int s, int kt) {
        char* base = smem + s * STAGE_B;
        const bf16* a = gA + kt * BK;
        const bf16* b = gB + kt * BK;
#pragma unroll
        for (int i = 0; i < 4; i++) {
            cp16(base + lrow[i] * (RS * 2) + lcol[i] * 2,
                 a + (size_t)lrow[i] * K + lcol[i]);
            cp16(base + TILE_B + lrow[i] * (RS * 2) + lcol[i] * 2,
                 b + (size_t)lrow[i] * K + lcol[i]);
        }
    };

    float acc[2][8][4];
#pragma unroll
    for (int mf = 0; mf < 2; mf++)
#pragma unroll
        for (int nf = 0; nf < 8; nf++)
#pragma unroll
            for (int q = 0; q < 4; q++) acc[mf][nf][q] = 0.f;

#pragma unroll
    for (int s = 0; s < STAGES - 1; s++) { load_stage(s, s); cp_commit(); }

    for (int kt = 0; kt < nkt; kt++) {
        cp_wait<STAGES - 2>();
        __syncthreads();
        const int nl = kt + STAGES - 1;
        if (nl < nkt) load_stage(nl % STAGES, nl);
        cp_commit();

        const uint32_t sa = sbase + (uint32_t)((kt % STAGES) * STAGE_B);
        const uint32_t sb = sa + TILE_B;
#pragma unroll
        for (int ks = 0; ks < 4; ks++) {
            uint32_t af[2][4], bq[4][4];
            ldsm4(af[0], sa + aoff[0] + ks * 32);
            ldsm4(af[1], sa + aoff[1] + ks * 32);
#pragma unroll
            for (int nfp = 0; nfp < 4; nfp++)
                ldsm4(bq[nfp], sb + boff[nfp] + ks * 32);
#pragma unroll
            for (int mf = 0; mf < 2; mf++)
#pragma unroll
                for (int nf = 0; nf < 8; nf++)
                    mma16(acc[mf][nf], af[mf], &bq[nf >> 1][(nf & 1) * 2]);
        }
    }

    // ---------------- epilogue (all cross-sub reads via L2) ----------------
    const int mode = S.mode;
#pragma unroll
    for (int mf = 0; mf < 2; mf++) {
#pragma unroll
        for (int nf = 0; nf < 8; nf++) {
            const int m1 = bm + m0 + mf * 16 + g;
            const int nn = bn + n0 + nf * 8 + t4 * 2;
            const size_t i1 = (size_t)m1 * N + nn;
            const size_t i2 = (size_t)(m1 + 8) * N + nn;
            const float* ac = acc[mf][nf];
            if (mode == 0 || mode == 3 || mode == 4) {
                float2 v1 = __ldcg((const float2*)(S.X1 + i1));
                float2 v2 = __ldcg((const float2*)(S.X1 + i2));
                if (mode == 3) {
                    float2 e1 = __ldcg((const float2*)(S.X3 + i1));
                    float2 e2 = __ldcg((const float2*)(S.X3 + i2));
                    int2 m1i = *(const int2*)(S.Msk + i1);
                    int2 m2i = *(const int2*)(S.Msk + i2);
                    v1.x -= DT_C * e1.x * (float)m1i.x;
                    v1.y -= DT_C * e1.y * (float)m1i.y;
                    v2.x -= DT_C * e2.x * (float)m2i.x;
                    v2.y -= DT_C * e2.y * (float)m2i.y;
                    *(float2*)(S.OutV + i1) = v1;
                    *(float2*)(S.OutV + i2) = v2;
                }
                float2 o1 = make_float2(v1.x - ac[0], v1.y - ac[1]);
                float2 o2 = make_float2(v2.x - ac[2], v2.y - ac[3]);
                if (mode != 4) {
                    *(float2*)(S.Out + i1) = o1;
                    *(float2*)(S.Out + i2) = o2;
                }
                *(__nv_bfloat162*)(S.Xb + i1) = tobf2(o1.x, o1.y);
                *(__nv_bfloat162*)(S.Xb + i2) = tobf2(o2.x, o2.y);
            } else {
                const float pen = (mode == 1) ? LAMB_C : 0.f;
                float2 v1 = __ldcg((const float2*)(S.X1 + i1));
                float2 v2 = __ldcg((const float2*)(S.X1 + i2));
                __nv_bfloat162 tb1 = ldcg_bf2(S.Xb + i1);
                __nv_bfloat162 tb2 = ldcg_bf2(S.Xb + i2);
                float2 e1, e2;
                if (mode == 1) {
                    float2 mm = *(const float2*)(S.X3 + nn);
                    e1 = make_float2(v1.x - mm.x, v1.y - mm.y);
                    e2 = make_float2(v2.x - mm.x, v2.y - mm.y);
                } else {
                    __nv_bfloat162 eb1 = ldcg_bf2(S.X3b + i1);
                    __nv_bfloat162 eb2 = ldcg_bf2(S.X3b + i2);
                    e1 = make_float2(__bfloat162float(eb1.x), __bfloat162float(eb1.y));
                    e2 = make_float2(__bfloat162float(eb2.x), __bfloat162float(eb2.y));
                }
                float vv[4] = {v1.x, v1.y, v2.x, v2.y};
                float tt[4] = {__bfloat162float(tb1.x), __bfloat162float(tb1.y),
                               __bfloat162float(tb2.x), __bfloat162float(tb2.y)};
                float ee[4] = {e1.x, e1.y, e2.x, e2.y};
                float nv[4], nt[4];
#pragma unroll
                for (int q = 0; q < 4; q++) {
                    const float deriv = 1.f - tt[q] * tt[q];
                    const float sg = (vv[q] > 0.f) ? 1.f : ((vv[q] < 0.f) ? -1.f : 0.f);
                    nv[q] = vv[q] + DT_C * (-ee[q] - pen * sg + deriv * ac[q]);
                    nt[q] = tanhf(nv[q]);
                }
                *(float2*)(S.Out + i1) = make_float2(nv[0], nv[1]);
                *(float2*)(S.Out + i2) = make_float2(nv[2], nv[3]);
                *(__nv_bfloat162*)(S.Xb + i1) = tobf2(nt[0], nt[1]);
                *(__nv_bfloat162*)(S.Xb + i2) = tobf2(nt[2], nt[3]);
            }
        }
    }
}

// --------------------------- mega kernel -----------------------------------
// Sub ids: 0=u2, 1=u1, 2=u0, 3=eE3s, 4=eE2, 5=eE1, 6=initE3, 7=sensory
// Iter layout (bid order): u2[512] u1[512] u0[256] eE3s[512] eE2[512] eE1[512]
struct MegaArgs {
    float *v0, *v1, *v2, *v3, *E3;
    bf16 *T0b, *T1b, *T2b, *E1b, *E2b, *E3b;
    const bf16 *W0b, *W1b, *W2b, *W0tb, *W1tb, *W2tb;
    const float* memv;
    const int* mask;
    float* out;
    int* ctr;
};

__global__ void __launch_bounds__(256, 2)
gemm_mega(MegaArgs M) {
    extern __shared__ char smem[];
    const int bid = blockIdx.x;
    int iter, s, lb;
    if (bid < 512) { iter = 19; s = 6; lb = bid; }
    else {
        int t = bid - 512;
        if (t < NFULL * CPI) {
            iter = t / CPI;
            int r = t - iter * CPI;
            if (r < 512)       { s = 0; lb = r; }
            else if (r < 1024) { s = 1; lb = r - 512; }
            else if (r < 1280) { s = 2; lb = r - 1024; }
            else if (r < 1792) { s = 3; lb = r - 1280; }
            else if (r < 2304) { s = 4; lb = r - 1792; }
            else               { s = 5; lb = r - 2304; }
        } else {
            int r = t - NFULL * CPI;
            iter = NFULL;
            if (r < 512)       { s = 0; lb = r; }
            else if (r < 1024) { s = 3; lb = r - 512; }
            else               { s = 7; lb = r - 1024; }
        }
    }

    // ------------------ dependency wait (fine-grained) ---------------------
    int* C = M.ctr;
    int w1 = -1, w2 = -1, t1 = 0, t2 = 0;
    switch (s) {
        case 0:  // u2 <- eE2(i-1), eE3s(i-1) | iter0 <- initE3
            if (iter == 0) { w1 = CTR_INIT; t1 = 512; }
            else { w1 = (iter - 1) * 8 + 4; t1 = 512;
                   w2 = (iter - 1) * 8 + 3; t2 = 512; }
            break;
        case 1:  // u1 <- eE1(i-1), eE2(i-1)
            if (iter > 0) { w1 = (iter - 1) * 8 + 5; t1 = 512;
                            w2 = (iter - 1) * 8 + 4; t2 = 512; }
            break;
        case 2:  // u0 <- eE1(i-1)
            if (iter > 0) { w1 = (iter - 1) * 8 + 5; t1 = 512; }
            break;
        case 3:  w1 = iter * 8 + 0; t1 = 512; break;                 // eE3s <- u2
        case 4:  w1 = iter * 8 + 0; t1 = 512;
                 w2 = iter * 8 + 1; t2 = 512; break;                 // eE2 <- u2,u1
        case 5:  w1 = iter * 8 + 1; t1 = 512;
                 w2 = iter * 8 + 2; t2 = 256; break;                 // eE1 <- u1,u0
        case 7:  w1 = NFULL * 8 + 3; t1 = 512; break;                // sensory
        default: break;
    }
    if (threadIdx.x == 0) {
        if (w1 >= 0) while (*(volatile int*)(C + w1) < t1) __nanosleep(64);
        if (w2 >= 0) while (*(volatile int*)(C + w2) < t2) __nanosleep(64);
    }
    __syncthreads();

    if (s == 7) {
        // final sensory: out = v3 - DT*E3*mask (grid-stride over 64 CTAs)
        const int total = BROWS * D1 / 4;
        for (int i = lb * 256 + threadIdx.x; i < total; i += 64 * 256) {
            float4 v = __ldcg((const float4*)M.v3 + i);
            float4 e = __ldcg((const float4*)M.E3 + i);
            int4 m = ((const int4*)M.mask)[i];
            float4 o;
            o.x = v.x - DT_C * e.x * (float)m.x;
            o.y = v.y - DT_C * e.y * (float)m.y;
            o.z = v.z - DT_C * e.z * (float)m.z;
            o.w = v.w - DT_C * e.w * (float)m.w;
            ((float4*)M.out)[i] = o;
        }
        return;
    }

    // ------------------------- build descriptor ----------------------------
    Sub S;
    switch (s) {
        case 0: S = {M.E3b, M.W2tb, M.v2, M.T2b, nullptr, M.E2b, nullptr,
                     M.v2, nullptr, D1, D1, 2, 16}; break;           // u2
        case 1: S = {M.E2b, M.W1tb, M.v1, M.T1b, nullptr, M.E1b, nullptr,
                     M.v1, nullptr, D1, D1, 2, 16}; break;           // u1
        case 2: S = {M.E1b, M.W0tb, M.v0, M.T0b, M.memv, nullptr, nullptr,
                     M.v0, nullptr, D0, D1, 1, 8}; break;            // u0
        case 3: S = {M.T2b, M.W2b, M.v3, M.E3b, M.E3, nullptr, M.mask,
                     M.E3, M.v3, D1, D1, 3, 16}; break;              // eE3s
        case 4: S = {M.T1b, M.W1b, M.v2, M.E2b, nullptr, nullptr, nullptr,
                     nullptr, nullptr, D1, D1, 4, 16}; break;        // eE2
        case 5: S = {M.T0b, M.W0b, M.v1, M.E1b, nullptr, nullptr, nullptr,
                     nullptr, nullptr, D1, D0, 4, 16}; break;        // eE1
        default: S = {M.T2b, M.W2b, M.v3, M.E3b, nullptr, nullptr, nullptr,
                      M.E3, nullptr, D1, D1, 0, 16}; break;          // initE3
    }

    gemm_core(S, lb, smem);

    // --------------------------- release -----------------------------------
    __threadfence();
    __syncthreads();
    if (threadIdx.x == 0) {
        const int my = (s == 6) ? CTR_INIT : iter * 8 + s;
        atomicAdd(C + my, 1);
    }
}

// --------------------------- small helper kernels --------------------------
__global__ void row_gemm(const float* __restrict__ in, const float* __restrict__ W,
                         float* __restrict__ out, int K) {
    const int n = blockIdx.x;
    float s = 0.f;
    for (int k = threadIdx.x; k < K; k += 256)
        s += tanhf(in[k]) * W[(size_t)n * K + k];
#pragma unroll
    for (int o = 16; o; o >>= 1) s += __shfl_down_sync(0xffffffffu, s, o);
    __shared__ float red[8];
    if ((threadIdx.x & 31) == 0) red[threadIdx.x >> 5] = s;
    __syncthreads();
    if (threadIdx.x == 0) {
        float t = 0.f;
#pragma unroll
        for (int w = 0; w < 8; w++) t += red[w];
        out[n] = t;
    }
}

__global__ void bcast2(const float* __restrict__ row, float* __restrict__ v,
                       bf16* __restrict__ t, int nmask, long total) {
    long i = (long)blockIdx.x * blockDim.x + threadIdx.x;
    const long stride = (long)gridDim.x * blockDim.x;
    for (; i < total; i += stride) {
        float x = row[i & nmask];
        v[i] = x;
        t[i] = __float2bfloat16_rn(tanhf(x));
    }
}

__global__ void zero_fill_b(bf16* __restrict__ b, long total) {
    long i = (long)blockIdx.x * blockDim.x + threadIdx.x;
    const long stride = (long)gridDim.x * blockDim.x;
    for (; i < total; i += stride) b[i] = __float2bfloat16_rn(0.f);
}

__global__ void zero_ctr(int* c) {
    if (threadIdx.x < 192) c[threadIdx.x] = 0;
}

__global__ void round_copy(const float* __restrict__ in, bf16* __restrict__ out,
                           long total) {
    long i = (long)blockIdx.x * blockDim.x + threadIdx.x;
    const long stride = (long)gridDim.x * blockDim.x;
    for (; i < total; i += stride) out[i] = __float2bfloat16_rn(in[i]);
}

__global__ void transpose_k(const float* __restrict__ in, bf16* __restrict__ out,
                            int R, int C) {
    __shared__ float t[32][33];
    const int bx = blockIdx.x * 32, by = blockIdx.y * 32;
#pragma unroll
    for (int i = 0; i < 32; i += 8)
        t[threadIdx.y + i][threadIdx.x] =
            in[(size_t)(by + threadIdx.y + i) * C + bx + threadIdx.x];
    __syncthreads();
#pragma unroll
    for (int i = 0; i < 32; i += 8)
        out[(size_t)(bx + threadIdx.y + i) * R + by + threadIdx.x] =
            __float2bfloat16_rn(t[threadIdx.x][threadIdx.y + i]);
}

// ------------------------------ orchestration ------------------------------
extern "C" void kernel_launch(void* const* d_in, const int* in_sizes, int n_in,
                              void* d_out, int out_size) {
    (void)in_sizes; (void)n_in; (void)out_size;
    const float* corrupt = (const float*)d_in[0];
    const float* memv    = (const float*)d_in[1];
    const float* W0      = (const float*)d_in[2];
    const float* W1      = (const float*)d_in[3];
    const float* W2      = (const float*)d_in[4];
    const int*   mask    = (const int*)d_in[5];
    float* out = (float*)d_out;

    MegaArgs M;
    int* ctr;
    float *r1, *r2;
    cudaGetSymbolAddress((void**)&M.v0, g_v0);
    cudaGetSymbolAddress((void**)&M.v1, g_v1);
    cudaGetSymbolAddress((void**)&M.v2, g_v2);
    cudaGetSymbolAddress((void**)&M.v3, g_v3);
    cudaGetSymbolAddress((void**)&M.E3, g_E3);
    cudaGetSymbolAddress((void**)&ctr, g_ctr);
    cudaGetSymbolAddress((void**)&M.T0b, g_T0b);
    cudaGetSymbolAddress((void**)&M.T1b, g_T1b);
    cudaGetSymbolAddress((void**)&M.T2b, g_T2b);
    cudaGetSymbolAddress((void**)&M.E1b, g_E1b);
    cudaGetSymbolAddress((void**)&M.E2b, g_E2b);
    cudaGetSymbolAddress((void**)&M.E3b, g_E3b);
    cudaGetSymbolAddress((void**)&M.W0b, g_W0b);
    cudaGetSymbolAddress((void**)&M.W1b, g_W1b);
    cudaGetSymbolAddress((void**)&M.W2b, g_W2b);
    cudaGetSymbolAddress((void**)&M.W0tb, g_W0tb);
    cudaGetSymbolAddress((void**)&M.W1tb, g_W1tb);
    cudaGetSymbolAddress((void**)&M.W2tb, g_W2tb);
    cudaGetSymbolAddress((void**)&r1, g_row1);
    cudaGetSymbolAddress((void**)&r2, g_row2);
    M.memv = memv; M.mask = mask; M.out = out; M.ctr = ctr;

    cudaFuncSetAttribute(gemm_mega, cudaFuncAttributeMaxDynamicSharedMemorySize,
                         SMEM_BYTES);

    // ------------------------------- init ----------------------------------
    round_copy<<<512, 256>>>(W0, (bf16*)M.W0b, (long)D1 * D0);
    round_copy<<<512, 256>>>(W1, (bf16*)M.W1b, (long)D1 * D1);
    round_copy<<<512, 256>>>(W2, (bf16*)M.W2b, (long)D1 * D1);
    const dim3 tb(32, 8);
    transpose_k<<<dim3(D0 / 32, D1 / 32), tb>>>(W0, (bf16*)M.W0tb, D1, D0);
    transpose_k<<<dim3(D1 / 32, D1 / 32), tb>>>(W1, (bf16*)M.W1tb, D1, D1);
    transpose_k<<<dim3(D1 / 32, D1 / 32), tb>>>(W2, (bf16*)M.W2tb, D1, D1);

    bcast2<<<1024, 256>>>(memv, M.v0, M.T0b, D0 - 1, (long)BROWS * D0);
    row_gemm<<<D1, 256>>>(memv, W0, r1, D0);
    bcast2<<<1024, 256>>>(r1, M.v1, M.T1b, D1 - 1, (long)BROWS * D1);
    row_gemm<<<D1, 256>>>(r1, W1, r2, D1);
    bcast2<<<1024, 256>>>(r2, M.v2, M.T2b, D1 - 1, (long)BROWS * D1);
    cudaMemcpyAsync(M.v3, corrupt, sizeof(float) * (size_t)BROWS * D1,
                    cudaMemcpyDeviceToDevice, 0);
    zero_fill_b<<<1024, 256>>>(M.E1b, (long)BROWS * D1);
    zero_fill_b<<<1024, 256>>>(M.E2b, (long)BROWS * D1);
    zero_ctr<<<1, 192>>>(ctr);

    // --------------- the whole 19-iteration loop in one launch -------------
    gemm_mega<<<GRID_MEGA, 256, SMEM_BYTES>>>(M);
}

// round 10
// speedup vs baseline: 7.5106x; 1.0505x over previous
#include <cuda_runtime.h>
#include <cuda_bf16.h>
#include <cstdint>

// ---------------------------------------------------------------------------
// Hierarchical PCN relaxation — mixed bf16/fp8 mma.sync + ldmatrix mega-launch.
//
// err GEMMs (E = v - T@W^T):       bf16 m16n8k16  (accuracy-critical)
// upd GEMMs (G = E@Wt, 100x damped): fp8 e4m3 m16n8k32 (2x rate)
//   Wt stored fp8 * 32 (avoid subnormals), epilogue acc * 1/32.
//   E kept dual: bf16 copy for the undamped -e epilogue term, fp8 for GEMM A.
// One mega-launch for all 19 iterations, fine-grained per-sub dep counters.
// iter0: u0/u1 folded into init (E1=E2=0 exactly). iter17: u0/eE1 dropped.
// iter18: eE3 fused with BOTH sensory updates, writes out directly (mode 5).
// ---------------------------------------------------------------------------

using bf16 = __nv_bfloat16;

namespace {
constexpr int BROWS = 4096;
constexpr int D0 = 1024;
constexpr int D1 = 2048;
constexpr float DT_C = 0.01f;
constexpr float LAMB_C = 0.001f;
constexpr float WSC = 32.0f;       // fp8 weight scale
constexpr float WSC_INV = 1.0f / 32.0f;

constexpr int STAGES = 3;
constexpr int SROW = 144;                      // smem row stride bytes
constexpr int TILE_B = 128 * SROW;             // 18432 B per operand tile
constexpr int STAGE_B = 2 * TILE_B;
constexpr int SMEM_BYTES = STAGES * STAGE_B;   // 110592

// mega-grid layout
constexpr int IT0 = 2048;                      // u2,eE3s,eE2,eE1
constexpr int FULLI = 2816;                    // u2,u1,u0,eE3s,eE2,eE1
constexpr int NFULL = 16;                      // iters 1..16
constexpr int IT17 = 2048;                     // u2,u1,eE3s,eE2
constexpr int IT18 = 1024;                     // u2,eE3(mode5)
constexpr int GRID_MEGA = 512 + IT0 + NFULL * FULLI + IT17 + IT18;  // 50688
constexpr int CTR_INIT = 152;                  // init-E3 counter slot
}

// ------------------------- scratch (__device__ globals) --------------------
__device__ __align__(16) float g_v0[(size_t)BROWS * D0];
__device__ __align__(16) float g_v1[(size_t)BROWS * D1];
__device__ __align__(16) float g_v2[(size_t)BROWS * D1];
__device__ __align__(16) float g_v3[(size_t)BROWS * D1];
__device__ __align__(16) float g_E3[(size_t)BROWS * D1];
__device__ __align__(16) bf16 g_T0b[(size_t)BROWS * D0];
__device__ __align__(16) bf16 g_T1b[(size_t)BROWS * D1];
__device__ __align__(16) bf16 g_T2b[(size_t)BROWS * D1];
__device__ __align__(16) bf16 g_E1b[(size_t)BROWS * D1];
__device__ __align__(16) bf16 g_E2b[(size_t)BROWS * D1];
__device__ __align__(16) uint8_t g_E1f[(size_t)BROWS * D1];
__device__ __align__(16) uint8_t g_E2f[(size_t)BROWS * D1];
__device__ __align__(16) uint8_t g_E3f[(size_t)BROWS * D1];
__device__ __align__(16) bf16 g_W0b[(size_t)D1 * D0];
__device__ __align__(16) bf16 g_W1b[(size_t)D1 * D1];
__device__ __align__(16) bf16 g_W2b[(size_t)D1 * D1];
__device__ __align__(16) uint8_t g_W0tf[(size_t)D0 * D1];
__device__ __align__(16) uint8_t g_W1tf[(size_t)D1 * D1];
__device__ __align__(16) uint8_t g_W2tf[(size_t)D1 * D1];
__device__ __align__(16) float g_row1[D1];
__device__ __align__(16) float g_row2[D1];
__device__ int g_ctr[192];

// ------------------------------ helpers ------------------------------------
__device__ __forceinline__ void cp16(void* dst, const void* src) {
    uint32_t d = (uint32_t)__cvta_generic_to_shared(dst);
    asm volatile("cp.async.cg.shared.global [%0], [%1], 16;" :: "r"(d), "l"(src));
}
__device__ __forceinline__ void cp_commit() {
    asm volatile("cp.async.commit_group;" ::: "memory");
}
template <int N>
__device__ __forceinline__ void cp_wait() {
    asm volatile("cp.async.wait_group %0;" :: "n"(N) : "memory");
}
__device__ __forceinline__ void ldsm4(uint32_t* r, uint32_t addr) {
    asm volatile("ldmatrix.sync.aligned.m8n8.x4.shared.b16 {%0,%1,%2,%3}, [%4];"
                 : "=r"(r[0]), "=r"(r[1]), "=r"(r[2]), "=r"(r[3]) : "r"(addr));
}
__device__ __forceinline__ void mma_bf16(float* c, const uint32_t* a, const uint32_t* b) {
    asm volatile(
        "mma.sync.aligned.m16n8k16.row.col.f32.bf16.bf16.f32 "
        "{%0,%1,%2,%3}, {%4,%5,%6,%7}, {%8,%9}, {%0,%1,%2,%3};"
        : "+f"(c[0]), "+f"(c[1]), "+f"(c[2]), "+f"(c[3])
        : "r"(a[0]), "r"(a[1]), "r"(a[2]), "r"(a[3]), "r"(b[0]), "r"(b[1]));
}
__device__ __forceinline__ void mma_fp8(float* c, const uint32_t* a, const uint32_t* b) {
    asm volatile(
        "mma.sync.aligned.m16n8k32.row.col.f32.e4m3.e4m3.f32 "
        "{%0,%1,%2,%3}, {%4,%5,%6,%7}, {%8,%9}, {%0,%1,%2,%3};"
        : "+f"(c[0]), "+f"(c[1]), "+f"(c[2]), "+f"(c[3])
        : "r"(a[0]), "r"(a[1]), "r"(a[2]), "r"(a[3]), "r"(b[0]), "r"(b[1]));
}
__device__ __forceinline__ __nv_bfloat162 tobf2(float x, float y) {
    return __floats2bfloat162_rn(x, y);
}
__device__ __forceinline__ __nv_bfloat162 ldcg_bf2(const bf16* p) {
    unsigned int u = __ldcg((const unsigned int*)p);
    return *reinterpret_cast<__nv_bfloat162*>(&u);
}
// pack two floats to e4m3x2 (low byte = first arg)
__device__ __forceinline__ uint16_t f2e4m3x2(float lo, float hi) {
    uint16_t r;
    asm("cvt.rn.satfinite.e4m3x2.f32 %0, %1, %2;" : "=h"(r) : "f"(hi), "f"(lo));
    return r;
}
__device__ __forceinline__ uint8_t f2e4m3(float x) {
    return (uint8_t)f2e4m3x2(x, 0.f);
}

// ------------------------- sub-GEMM descriptor -----------------------------
// acc[m,n] = sum_k A[bm+m,k]*B[bn+n,k]
// mode 0 initE3:   E = X1 - acc;  Out=E3 f32, Xf=E3f
// mode 3 eE3s:     vnew = X1 - DT*X3*Msk; OutV=vnew(v3); E=vnew-acc; Out=E3, Xf
// mode 5 eE3fin:   vnew = X1 - DT*X3*Msk; E=vnew-acc; Out = vnew - DT*E*Msk
// mode 4 eE1/eE2:  E = X1 - acc; Xb=bf16(E), Xf=fp8(E)
// mode 1 u0:       e = X1 - X3[n] (memv), pen=LAMB; Out=nv, Xb=tanh; acc*gs
// mode 2 u1/u2:    e = bf16 X3b[m,n], pen=0;  acc*gs
struct Sub {
    const void *A, *B;      // byte-addressed operand bases
    const float* X1;
    bf16* Xb;
    uint8_t* Xf;
    const float* X3;
    const bf16* X3b;
    const int* Msk;
    float* Out;
    float* OutV;
    int N, K, mode, nbx;
    float gs;
};

template <int ESZ>
__device__ __forceinline__ void gemm_core(const Sub& S, int lbid, char* smem) {
    const uint32_t sbase = (uint32_t)__cvta_generic_to_shared(smem);
    const int tid = threadIdx.x;
    const int bn = (lbid % S.nbx) * 128;
    const int bm = (lbid / S.nbx) * 128;
    const int K = S.K, N = S.N;
    const int rowb = K * ESZ;
    const char* gA = (const char*)S.A + (size_t)bm * rowb;
    const char* gB = (const char*)S.B + (size_t)bn * rowb;
    const int nkt = rowb / 128;      // 128 bytes of K per tile

    const int warp = tid >> 5, lane = tid & 31;
    const int m0 = (warp & 3) * 32, n0 = (warp >> 2) * 64;
    const int g = lane >> 2, t4 = lane & 3;

    uint32_t aoff[2], boff[4];
#pragma unroll
    for (int mf = 0; mf < 2; mf++)
        aoff[mf] = (uint32_t)((m0 + mf * 16 + (lane & 15)) * SROW +
                              (lane >> 4) * 16);
#pragma unroll
    for (int nfp = 0; nfp < 4; nfp++)
        boff[nfp] = (uint32_t)((n0 + nfp * 16 + (lane & 7) +
                                ((lane >> 4) & 1) * 8) * SROW +
                               ((lane >> 3) & 1) * 16);

    int lrow[4], bcol[4];
#pragma unroll
    for (int i = 0; i < 4; i++) {
        const int c = tid + i * 256;
        lrow[i] = c >> 3;
        bcol[i] = (c & 7) * 16;       // byte offset within 128B k-chunk
    }

    auto load_stage = [&](int s, int kt) {
        char* base = smem + s * STAGE_B;
        const char* a = gA + kt * 128;
        const char* b = gB + kt * 128;
#pragma unroll
        for (int i = 0; i < 4; i++) {
            cp16(base + lrow[i] * SROW + bcol[i],
                 a + (size_t)lrow[i] * rowb + bcol[i]);
            cp16(base + TILE_B + lrow[i] * SROW + bcol[i],
                 b + (size_t)lrow[i] * rowb + bcol[i]);
        }
    };

    float acc[2][8][4];
#pragma unroll
    for (int mf = 0; mf < 2; mf++)
#pragma unroll
        for (int nf = 0; nf < 8; nf++)
#pragma unroll
            for (int q = 0; q < 4; q++) acc[mf][nf][q] = 0.f;

#pragma unroll
    for (int s = 0; s < STAGES - 1; s++) { load_stage(s, s); cp_commit(); }

    for (int kt = 0; kt < nkt; kt++) {
        cp_wait<STAGES - 2>();
        __syncthreads();
        const int nl = kt + STAGES - 1;
        if (nl < nkt) load_stage(nl % STAGES, nl);
        cp_commit();

        const uint32_t sa = sbase + (uint32_t)((kt % STAGES) * STAGE_B);
        const uint32_t sb = sa + TILE_B;
#pragma unroll
        for (int ks = 0; ks < 4; ks++) {
            uint32_t af[2][4], bq[4][4];
            ldsm4(af[0], sa + aoff[0] + ks * 32);
            ldsm4(af[1], sa + aoff[1] + ks * 32);
#pragma unroll
            for (int nfp = 0; nfp < 4; nfp++)
                ldsm4(bq[nfp], sb + boff[nfp] + ks * 32);
#pragma unroll
            for (int mf = 0; mf < 2; mf++)
#pragma unroll
                for (int nf = 0; nf < 8; nf++) {
                    if (ESZ == 2)
                        mma_bf16(acc[mf][nf], af[mf], &bq[nf >> 1][(nf & 1) * 2]);
                    else
                        mma_fp8(acc[mf][nf], af[mf], &bq[nf >> 1][(nf & 1) * 2]);
                }
        }
    }

    // ------------------------------ epilogue -------------------------------
    const int mode = S.mode;
    const float gs = S.gs;
#pragma unroll
    for (int mf = 0; mf < 2; mf++) {
#pragma unroll
        for (int nf = 0; nf < 8; nf++) {
            const int m1 = bm + m0 + mf * 16 + g;
            const int nn = bn + n0 + nf * 8 + t4 * 2;
            const size_t i1 = (size_t)m1 * N + nn;
            const size_t i2 = (size_t)(m1 + 8) * N + nn;
            const float a0 = acc[mf][nf][0] * gs, a1 = acc[mf][nf][1] * gs;
            const float a2 = acc[mf][nf][2] * gs, a3 = acc[mf][nf][3] * gs;
            if (mode != 1 && mode != 2) {
                // --- err family (0 initE3, 3 eE3s, 4 eE1/eE2, 5 final) ---
                float2 v1 = __ldcg((const float2*)(S.X1 + i1));
                float2 v2 = __ldcg((const float2*)(S.X1 + i2));
                int2 m1i = {}, m2i = {};
                if (mode == 3 || mode == 5) {
                    float2 e1 = __ldcg((const float2*)(S.X3 + i1));
                    float2 e2 = __ldcg((const float2*)(S.X3 + i2));
                    m1i = *(const int2*)(S.Msk + i1);
                    m2i = *(const int2*)(S.Msk + i2);
                    v1.x -= DT_C * e1.x * (float)m1i.x;
                    v1.y -= DT_C * e1.y * (float)m1i.y;
                    v2.x -= DT_C * e2.x * (float)m2i.x;
                    v2.y -= DT_C * e2.y * (float)m2i.y;
                    if (mode == 3) {
                        *(float2*)(S.OutV + i1) = v1;
                        *(float2*)(S.OutV + i2) = v2;
                    }
                }
                float2 o1 = make_float2(v1.x - a0, v1.y - a1);
                float2 o2 = make_float2(v2.x - a2, v2.y - a3);
                if (mode == 0 || mode == 3) {
                    *(float2*)(S.Out + i1) = o1;
                    *(float2*)(S.Out + i2) = o2;
                }
                if (mode == 5) {
                    float2 w1, w2;
                    w1.x = v1.x - DT_C * o1.x * (float)m1i.x;
                    w1.y = v1.y - DT_C * o1.y * (float)m1i.y;
                    w2.x = v2.x - DT_C * o2.x * (float)m2i.x;
                    w2.y = v2.y - DT_C * o2.y * (float)m2i.y;
                    *(float2*)(S.Out + i1) = w1;
                    *(float2*)(S.Out + i2) = w2;
                } else {
                    if (mode == 4) {
                        *(__nv_bfloat162*)(S.Xb + i1) = tobf2(o1.x, o1.y);
                        *(__nv_bfloat162*)(S.Xb + i2) = tobf2(o2.x, o2.y);
                    }
                    *(uint16_t*)(S.Xf + i1) = f2e4m3x2(o1.x, o1.y);
                    *(uint16_t*)(S.Xf + i2) = f2e4m3x2(o2.x, o2.y);
                }
            } else {
                // --- upd family (1 u0, 2 u1/u2) ---
                const float pen = (mode == 1) ? LAMB_C : 0.f;
                float2 v1 = __ldcg((const float2*)(S.X1 + i1));
                float2 v2 = __ldcg((const float2*)(S.X1 + i2));
                __nv_bfloat162 tb1 = ldcg_bf2(S.Xb + i1);
                __nv_bfloat162 tb2 = ldcg_bf2(S.Xb + i2);
                float2 e1, e2;
                if (mode == 1) {
                    float2 mm = *(const float2*)(S.X3 + nn);
                    e1 = make_float2(v1.x - mm.x, v1.y - mm.y);
                    e2 = make_float2(v2.x - mm.x, v2.y - mm.y);
                } else {
                    __nv_bfloat162 eb1 = ldcg_bf2(S.X3b + i1);
                    __nv_bfloat162 eb2 = ldcg_bf2(S.X3b + i2);
                    e1 = make_float2(__bfloat162float(eb1.x), __bfloat162float(eb1.y));
                    e2 = make_float2(__bfloat162float(eb2.x), __bfloat162float(eb2.y));
                }
                float vv[4] = {v1.x, v1.y, v2.x, v2.y};
                float tt[4] = {__bfloat162float(tb1.x), __bfloat162float(tb1.y),
                               __bfloat162float(tb2.x), __bfloat162float(tb2.y)};
                float ee[4] = {e1.x, e1.y, e2.x, e2.y};
                float aa[4] = {a0, a1, a2, a3};
                float nv[4], nt[4];
#pragma unroll
                for (int q = 0; q < 4; q++) {
                    const float deriv = 1.f - tt[q] * tt[q];
                    const float sg = (vv[q] > 0.f) ? 1.f : ((vv[q] < 0.f) ? -1.f : 0.f);
                    nv[q] = vv[q] + DT_C * (-ee[q] - pen * sg + deriv * aa[q]);
                    nt[q] = tanhf(nv[q]);
                }
                *(float2*)(S.Out + i1) = make_float2(nv[0], nv[1]);
                *(float2*)(S.Out + i2) = make_float2(nv[2], nv[3]);
                *(__nv_bfloat162*)(S.Xb + i1) = tobf2(nt[0], nt[1]);
                *(__nv_bfloat162*)(S.Xb + i2) = tobf2(nt[2], nt[3]);
            }
        }
    }
}

// --------------------------- mega kernel -----------------------------------
// Sub ids: 0=u2, 1=u1, 2=u0, 3=eE3s(/mode5 @it18), 4=eE2, 5=eE1, 6=initE3
struct MegaArgs {
    float *v0, *v1, *v2, *v3, *E3;
    bf16 *T0b, *T1b, *T2b, *E1b, *E2b;
    uint8_t *E1f, *E2f, *E3f;
    const bf16 *W0b, *W1b, *W2b;
    const uint8_t *W0tf, *W1tf, *W2tf;
    const float* memv;
    const int* mask;
    float* out;
    int* ctr;
};

__global__ void __launch_bounds__(256, 2)
gemm_mega(MegaArgs M) {
    extern __shared__ char smem[];
    const int bid = blockIdx.x;
    int iter = 0, s, lb;
    if (bid < 512) { s = 6; lb = bid; }
    else {
        int t = bid - 512;
        if (t < IT0) {                         // iter 0: u2 eE3s eE2 eE1
            iter = 0;
            if (t < 512)        { s = 0; lb = t; }
            else if (t < 1024)  { s = 3; lb = t - 512; }
            else if (t < 1536)  { s = 4; lb = t - 1024; }
            else                { s = 5; lb = t - 1536; }
        } else if ((t -= IT0) < NFULL * FULLI) {   // iters 1..16 full
            iter = 1 + t / FULLI;
            int r = t % FULLI;
            if (r < 512)        { s = 0; lb = r; }
            else if (r < 1024)  { s = 1; lb = r - 512; }
            else if (r < 1280)  { s = 2; lb = r - 1024; }
            else if (r < 1792)  { s = 3; lb = r - 1280; }
            else if (r < 2304)  { s = 4; lb = r - 1792; }
            else                { s = 5; lb = r - 2304; }
        } else if ((t -= NFULL * FULLI) < IT17) {  // iter 17: u2 u1 eE3s eE2
            iter = 17;
            if (t < 512)        { s = 0; lb = t; }
            else if (t < 1024)  { s = 1; lb = t - 512; }
            else if (t < 1536)  { s = 3; lb = t - 1024; }
            else                { s = 4; lb = t - 1536; }
        } else {                                    // iter 18: u2 eE3(mode5)
            t -= IT17;
            iter = 18;
            if (t < 512)        { s = 0; lb = t; }
            else                { s = 3; lb = t - 512; }
        }
    }

    // ------------------ dependency wait (fine-grained) ---------------------
    int* C = M.ctr;
    int w1 = -1, w2 = -1, t1 = 0, t2 = 0;
    switch (s) {
        case 0:
            if (iter == 0) { w1 = CTR_INIT; t1 = 512; }
            else { w1 = (iter - 1) * 8 + 4; t1 = 512;
                   w2 = (iter - 1) * 8 + 3; t2 = 512; }
            break;
        case 1: w1 = (iter - 1) * 8 + 5; t1 = 512;
                w2 = (iter - 1) * 8 + 4; t2 = 512; break;
        case 2: w1 = (iter - 1) * 8 + 5; t1 = 512; break;
        case 3: w1 = iter * 8 + 0; t1 = 512; break;
        case 4:
            if (iter == 0) { w1 = 0; t1 = 512; }
            else { w1 = iter * 8 + 0; t1 = 512;
                   w2 = iter * 8 + 1; t2 = 512; }
            break;
        case 5:
            if (iter > 0) { w1 = iter * 8 + 1; t1 = 512;
                            w2 = iter * 8 + 2; t2 = 256; }
            break;
        default: break;
    }
    if (threadIdx.x == 0) {
        if (w1 >= 0) while (*(volatile int*)(C + w1) < t1) __nanosleep(64);
        if (w2 >= 0) while (*(volatile int*)(C + w2) < t2) __nanosleep(64);
    }
    __syncthreads();

    // ------------------------- build descriptor ----------------------------
    Sub S;
    if (s == 0) {        // u2 (fp8)
        S = {M.E3f, M.W2tf, M.v2, M.T2b, nullptr, nullptr, M.E2b, nullptr,
             M.v2, nullptr, D1, D1, 2, 16, WSC_INV};
    } else if (s == 1) { // u1 (fp8)
        S = {M.E2f, M.W1tf, M.v1, M.T1b, nullptr, nullptr, M.E1b, nullptr,
             M.v1, nullptr, D1, D1, 2, 16, WSC_INV};
    } else if (s == 2) { // u0 (fp8)
        S = {M.E1f, M.W0tf, M.v0, M.T0b, nullptr, M.memv, nullptr, nullptr,
             M.v0, nullptr, D0, D1, 1, 8, WSC_INV};
    } else if (s == 3) {
        if (iter == 18)  // final: fused double-sensory, writes out
            S = {M.T2b, M.W2b, M.v3, nullptr, nullptr, M.E3, nullptr, M.mask,
                 M.out, nullptr, D1, D1, 5, 16, 1.f};
        else             // eE3s
            S = {M.T2b, M.W2b, M.v3, nullptr, M.E3f, M.E3, nullptr, M.mask,
                 M.E3, M.v3, D1, D1, 3, 16, 1.f};
    } else if (s == 4) { // eE2
        S = {M.T1b, M.W1b, M.v2, M.E2b, M.E2f, nullptr, nullptr, nullptr,
             nullptr, nullptr, D1, D1, 4, 16, 1.f};
    } else if (s == 5) { // eE1
        S = {M.T0b, M.W0b, M.v1, M.E1b, M.E1f, nullptr, nullptr, nullptr,
             nullptr, nullptr, D1, D0, 4, 16, 1.f};
    } else {             // initE3
        S = {M.T2b, M.W2b, M.v3, nullptr, M.E3f, nullptr, nullptr, nullptr,
             M.E3, nullptr, D1, D1, 0, 16, 1.f};
    }

    if (s <= 2) gemm_core<1>(S, lb, smem);
    else        gemm_core<2>(S, lb, smem);

    // --------------------------- release -----------------------------------
    __threadfence();
    __syncthreads();
    if (threadIdx.x == 0) {
        const int my = (s == 6) ? CTR_INIT : iter * 8 + s;
        atomicAdd(C + my, 1);
    }
}

// --------------------------- small helper kernels --------------------------
__global__ void row_gemm(const float* __restrict__ in, const float* __restrict__ W,
                         float* __restrict__ out, int K) {
    const int n = blockIdx.x;
    float s = 0.f;
    for (int k = threadIdx.x; k < K; k += 256)
        s += tanhf(in[k]) * W[(size_t)n * K + k];
#pragma unroll
    for (int o = 16; o; o >>= 1) s += __shfl_down_sync(0xffffffffu, s, o);
    __shared__ float red[8];
    if ((threadIdx.x & 31) == 0) red[threadIdx.x >> 5] = s;
    __syncthreads();
    if (threadIdx.x == 0) {
        float t = 0.f;
#pragma unroll
        for (int w = 0; w < 8; w++) t += red[w];
        out[n] = t;
    }
}

// layers 1/2: v = row, T = bf16(tanh(row))
__global__ void bcast2(const float* __restrict__ row, float* __restrict__ v,
                       bf16* __restrict__ t, int nmask, long total) {
    long i = (long)blockIdx.x * blockDim.x + threadIdx.x;
    const long stride = (long)gridDim.x * blockDim.x;
    for (; i < total; i += stride) {
        float x = row[i & nmask];
        v[i] = x;
        t[i] = __float2bfloat16_rn(tanhf(x));
    }
}

// layer 0 with folded iter-0 update: v0 = mem - DT*LAMB*sign(mem)
__global__ void bcast0(const float* __restrict__ row, float* __restrict__ v,
                       bf16* __restrict__ t, int nmask, long total) {
    long i = (long)blockIdx.x * blockDim.x + threadIdx.x;
    const long stride = (long)gridDim.x * blockDim.x;
    for (; i < total; i += stride) {
        float x = row[i & nmask];
        float sg = (x > 0.f) ? 1.f : ((x < 0.f) ? -1.f : 0.f);
        float nv = x - DT_C * LAMB_C * sg;
        v[i] = nv;
        t[i] = __float2bfloat16_rn(tanhf(nv));
    }
}

__global__ void zero_bytes(char* __restrict__ p, long bytes) {
    long i = (long)blockIdx.x * blockDim.x + threadIdx.x;
    const long stride = (long)gridDim.x * blockDim.x;
    const long n = bytes / 16;
    for (; i < n; i += stride) ((int4*)p)[i] = make_int4(0, 0, 0, 0);
}

__global__ void zero_ctr(int* c) { if (threadIdx.x < 192) c[threadIdx.x] = 0; }

__global__ void round_copy(const float* __restrict__ in, bf16* __restrict__ out,
                           long total) {
    long i = (long)blockIdx.x * blockDim.x + threadIdx.x;
    const long stride = (long)gridDim.x * blockDim.x;
    for (; i < total; i += stride) out[i] = __float2bfloat16_rn(in[i]);
}

// out[c*R + r] = e4m3(in[r*C + c] * WSC)
__global__ void transpose_f8(const float* __restrict__ in, uint8_t* __restrict__ out,
                             int R, int C) {
    __shared__ float t[32][33];
    const int bx = blockIdx.x * 32, by = blockIdx.y * 32;
#pragma unroll
    for (int i = 0; i < 32; i += 8)
        t[threadIdx.y + i][threadIdx.x] =
            in[(size_t)(by + threadIdx.y + i) * C + bx + threadIdx.x];
    __syncthreads();
#pragma unroll
    for (int i = 0; i < 32; i += 8)
        out[(size_t)(bx + threadIdx.y + i) * R + by + threadIdx.x] =
            f2e4m3(t[threadIdx.x][threadIdx.y + i] * WSC);
}

// ------------------------------ orchestration ------------------------------
extern "C" void kernel_launch(void* const* d_in, const int* in_sizes, int n_in,
                              void* d_out, int out_size) {
    (void)in_sizes; (void)n_in; (void)out_size;
    const float* corrupt = (const float*)d_in[0];
    const float* memv    = (const float*)d_in[1];
    const float* W0      = (const float*)d_in[2];
    const float* W1      = (const float*)d_in[3];
    const float* W2      = (const float*)d_in[4];
    const int*   mask    = (const int*)d_in[5];
    float* out = (float*)d_out;

    MegaArgs M;
    int* ctr;
    float *r1, *r2;
    cudaGetSymbolAddress((void**)&M.v0, g_v0);
    cudaGetSymbolAddress((void**)&M.v1, g_v1);
    cudaGetSymbolAddress((void**)&M.v2, g_v2);
    cudaGetSymbolAddress((void**)&M.v3, g_v3);
    cudaGetSymbolAddress((void**)&M.E3, g_E3);
    cudaGetSymbolAddress((void**)&ctr, g_ctr);
    cudaGetSymbolAddress((void**)&M.T0b, g_T0b);
    cudaGetSymbolAddress((void**)&M.T1b, g_T1b);
    cudaGetSymbolAddress((void**)&M.T2b, g_T2b);
    cudaGetSymbolAddress((void**)&M.E1b, g_E1b);
    cudaGetSymbolAddress((void**)&M.E2b, g_E2b);
    cudaGetSymbolAddress((void**)&M.E1f, g_E1f);
    cudaGetSymbolAddress((void**)&M.E2f, g_E2f);
    cudaGetSymbolAddress((void**)&M.E3f, g_E3f);
    cudaGetSymbolAddress((void**)&M.W0b, g_W0b);
    cudaGetSymbolAddress((void**)&M.W1b, g_W1b);
    cudaGetSymbolAddress((void**)&M.W2b, g_W2b);
    cudaGetSymbolAddress((void**)&M.W0tf, g_W0tf);
    cudaGetSymbolAddress((void**)&M.W1tf, g_W1tf);
    cudaGetSymbolAddress((void**)&M.W2tf, g_W2tf);
    cudaGetSymbolAddress((void**)&r1, g_row1);
    cudaGetSymbolAddress((void**)&r2, g_row2);
    M.memv = memv; M.mask = mask; M.out = out; M.ctr = ctr;

    cudaFuncSetAttribute(gemm_mega, cudaFuncAttributeMaxDynamicSharedMemorySize,
                         SMEM_BYTES);

    // ------------------------------- init ----------------------------------
    round_copy<<<512, 256>>>(W0, (bf16*)M.W0b, (long)D1 * D0);
    round_copy<<<512, 256>>>(W1, (bf16*)M.W1b, (long)D1 * D1);
    round_copy<<<512, 256>>>(W2, (bf16*)M.W2b, (long)D1 * D1);
    const dim3 tb(32, 8);
    transpose_f8<<<dim3(D0 / 32, D1 / 32), tb>>>(W0, (uint8_t*)M.W0tf, D1, D0);
    transpose_f8<<<dim3(D1 / 32, D1 / 32), tb>>>(W1, (uint8_t*)M.W1tf, D1, D1);
    transpose_f8<<<dim3(D1 / 32, D1 / 32), tb>>>(W2, (uint8_t*)M.W2tf, D1, D1);

    bcast0<<<1024, 256>>>(memv, M.v0, M.T0b, D0 - 1, (long)BROWS * D0);
    row_gemm<<<D1, 256>>>(memv, W0, r1, D0);
    bcast2<<<1024, 256>>>(r1, M.v1, M.T1b, D1 - 1, (long)BROWS * D1);
    row_gemm<<<D1, 256>>>(r1, W1, r2, D1);
    bcast2<<<1024, 256>>>(r2, M.v2, M.T2b, D1 - 1, (long)BROWS * D1);
    cudaMemcpyAsync(M.v3, corrupt, sizeof(float) * (size_t)BROWS * D1,
                    cudaMemcpyDeviceToDevice, 0);
    // E2b must start at exactly zero (read by u2(0) e-term); E1b/E1f/E2f for safety
    zero_bytes<<<1024, 256>>>((char*)M.E1b, (long)BROWS * D1 * 2);
    zero_bytes<<<1024, 256>>>((char*)M.E2b, (long)BROWS * D1 * 2);
    zero_bytes<<<1024, 256>>>((char*)M.E1f, (long)BROWS * D1);
    zero_bytes<<<1024, 256>>>((char*)M.E2f, (long)BROWS * D1);
    zero_ctr<<<1, 192>>>(ctr);

    // --------------- everything else in ONE mega-launch --------------------
    gemm_mega<<<GRID_MEGA, 256, SMEM_BYTES>>>(M);
}